// round 11
// baseline (speedup 1.0000x reference)
#include <cuda_runtime.h>
#include <cstdint>

#define N_NODES 100000
#define N_EDGES 300000
#define HID 256
#define SCAN_B 1024
#define N_BLK ((N_NODES + SCAN_B - 1) / SCAN_B)   // 98

// ---------------- scratch ----------------
__device__ float g_H[(size_t)N_NODES * HID];
__device__ float g_AGG[(size_t)N_NODES * HID];
__device__ float g_WT[HID * HID];       // gc2_weight^T, tf32-rounded
__device__ float g_W0[HID * 512];       // fc weights, tf32-rounded
__device__ float g_W1[HID * 256];
__device__ float g_W2[HID * 128];
__device__ float g_norm_out[N_NODES];
__device__ float g_norm_in[N_NODES];
__device__ int g_din[N_NODES];
__device__ int g_dout[N_NODES];
__device__ int g_row_ptr[N_NODES + 1];
__device__ int g_cursor[N_NODES];
__device__ int g_col[N_EDGES];
__device__ int g_blksum[N_BLK];

__device__ __forceinline__ float tf32_rn(float x) {
    uint32_t r;
    asm("cvt.rna.tf32.f32 %0, %1;" : "=r"(r) : "f"(x));
    return __uint_as_float(r);
}
__device__ __forceinline__ void mma_tf32(float* c, const float* a, const float* b) {
    asm volatile(
        "mma.sync.aligned.m16n8k8.row.col.f32.tf32.tf32.f32 "
        "{%0,%1,%2,%3}, {%4,%5,%6,%7}, {%8,%9}, {%0,%1,%2,%3};"
        : "+f"(c[0]), "+f"(c[1]), "+f"(c[2]), "+f"(c[3])
        : "r"(__float_as_uint(a[0])), "r"(__float_as_uint(a[1])),
          "r"(__float_as_uint(a[2])), "r"(__float_as_uint(a[3])),
          "r"(__float_as_uint(b[0])), "r"(__float_as_uint(b[1])));
}

// ---------------- weight pre-conversion (fp32 -> tf32-rounded fp32) ----------------
__global__ void cvt_weights(const float* __restrict__ W, float* __restrict__ out, int n4) {
    int i = blockIdx.x * blockDim.x + threadIdx.x;
    if (i < n4) {
        float4 v = reinterpret_cast<const float4*>(W)[i];
        v.x = tf32_rn(v.x); v.y = tf32_rn(v.y); v.z = tf32_rn(v.z); v.w = tf32_rn(v.w);
        reinterpret_cast<float4*>(out)[i] = v;
    }
}

// ---------------- CSR build ----------------
__global__ void hist_kernel(const int* __restrict__ src, const int* __restrict__ dst) {
    int e = blockIdx.x * blockDim.x + threadIdx.x;
    if (e < N_EDGES) {
        atomicAdd(&g_dout[src[e]], 1);
        atomicAdd(&g_din[dst[e]], 1);
    }
}
__global__ void scan_a() {
    __shared__ int sh[SCAN_B];
    int t = threadIdx.x, idx = blockIdx.x * SCAN_B + t;
    int v = (idx < N_NODES) ? g_din[idx] : 0;
    sh[t] = v;
    __syncthreads();
#pragma unroll
    for (int off = 1; off < SCAN_B; off <<= 1) {
        int add = (t >= off) ? sh[t - off] : 0;
        __syncthreads();
        sh[t] += add;
        __syncthreads();
    }
    if (idx < N_NODES) g_row_ptr[idx + 1] = sh[t];
    if (t == SCAN_B - 1) g_blksum[blockIdx.x] = sh[t];
}
__global__ void scan_c() {
    __shared__ int red[256];
    const int t = threadIdx.x;
    const int chunk = (blockIdx.x * 256) / SCAN_B;
    int part = 0;
    for (int i = t; i < chunk; i += 256) part += g_blksum[i];
    red[t] = part;
    __syncthreads();
#pragma unroll
    for (int o = 128; o > 0; o >>= 1) {
        if (t < o) red[t] += red[t + o];
        __syncthreads();
    }
    const int base = red[0];
    int idx = blockIdx.x * 256 + t;
    if (idx == 0) g_row_ptr[0] = 0;
    if (idx < N_NODES) {
        int inc = g_row_ptr[idx + 1] + base;
        g_row_ptr[idx + 1] = inc;
        g_cursor[idx] = inc - g_din[idx];
        g_norm_in[idx]  = rsqrtf(fmaxf((float)g_din[idx], 1.f));
        g_norm_out[idx] = rsqrtf(fmaxf((float)g_dout[idx], 1.f));
    }
}
__global__ void scatter_kernel(const int* __restrict__ src, const int* __restrict__ dst) {
    int e = blockIdx.x * blockDim.x + threadIdx.x;
    if (e < N_EDGES) {
        int pos = atomicAdd(&g_cursor[dst[e]], 1);
        g_col[pos] = src[e];
    }
}

// ---------------- CSR SpMM (layer 1): gather H[src]*norm_out[src], fused epilogue ----
__global__ void __launch_bounds__(256)
spmm_scaled(const float* __restrict__ X, float* __restrict__ out, const float* __restrict__ bias) {
    int node = blockIdx.x * 4 + (threadIdx.x >> 6);
    if (node >= N_NODES) return;
    int lane = threadIdx.x & 63;
    int beg = g_row_ptr[node], end = g_row_ptr[node + 1];
    float4 acc = make_float4(0.f, 0.f, 0.f, 0.f);
    int e = beg;
    for (; e + 2 <= end; e += 2) {
        int s0 = __ldg(&g_col[e]), s1 = __ldg(&g_col[e + 1]);
        float w0 = __ldg(&g_norm_out[s0]), w1 = __ldg(&g_norm_out[s1]);
        float4 v0 = __ldg(reinterpret_cast<const float4*>(X + (size_t)s0 * HID + lane * 4));
        float4 v1 = __ldg(reinterpret_cast<const float4*>(X + (size_t)s1 * HID + lane * 4));
        acc.x += v0.x * w0 + v1.x * w1;
        acc.y += v0.y * w0 + v1.y * w1;
        acc.z += v0.z * w0 + v1.z * w1;
        acc.w += v0.w * w0 + v1.w * w1;
    }
    if (e < end) {
        int s = __ldg(&g_col[e]);
        float w = __ldg(&g_norm_out[s]);
        float4 v = __ldg(reinterpret_cast<const float4*>(X + (size_t)s * HID + lane * 4));
        acc.x += v.x * w; acc.y += v.y * w; acc.z += v.z * w; acc.w += v.w * w;
    }
    float ni = g_norm_in[node];
    float no = g_norm_out[node];
    float4 b = *reinterpret_cast<const float4*>(bias + lane * 4);
    acc.x = fmaxf(acc.x * ni + b.x, 0.f) * no;
    acc.y = fmaxf(acc.y * ni + b.y, 0.f) * no;
    acc.z = fmaxf(acc.z * ni + b.z, 0.f) * no;
    acc.w = fmaxf(acc.w * ni + b.w, 0.f) * no;
    *reinterpret_cast<float4*>(out + (size_t)node * HID + lane * 4) = acc;
}

// ---------------- CSR SpMM (layer 2): plain gather-sum; output tf32-pre-rounded ----
__global__ void __launch_bounds__(256)
spmm_plain(const float* __restrict__ X, float* __restrict__ out) {
    int node = blockIdx.x * 4 + (threadIdx.x >> 6);
    if (node >= N_NODES) return;
    int lane = threadIdx.x & 63;
    int beg = g_row_ptr[node], end = g_row_ptr[node + 1];
    float4 acc = make_float4(0.f, 0.f, 0.f, 0.f);
    int e = beg;
    for (; e + 2 <= end; e += 2) {
        int s0 = __ldg(&g_col[e]), s1 = __ldg(&g_col[e + 1]);
        float4 v0 = __ldg(reinterpret_cast<const float4*>(X + (size_t)s0 * HID + lane * 4));
        float4 v1 = __ldg(reinterpret_cast<const float4*>(X + (size_t)s1 * HID + lane * 4));
        acc.x += v0.x + v1.x; acc.y += v0.y + v1.y;
        acc.z += v0.z + v1.z; acc.w += v0.w + v1.w;
    }
    if (e < end) {
        int s = __ldg(&g_col[e]);
        float4 v = __ldg(reinterpret_cast<const float4*>(X + (size_t)s * HID + lane * 4));
        acc.x += v.x; acc.y += v.y; acc.z += v.z; acc.w += v.w;
    }
    // pre-round for the consuming tf32 GEMM (CVTA=false path)
    acc.x = tf32_rn(acc.x); acc.y = tf32_rn(acc.y);
    acc.z = tf32_rn(acc.z); acc.w = tf32_rn(acc.w);
    *reinterpret_cast<float4*>(out + (size_t)node * HID + lane * 4) = acc;
}

// ---------------- tensor-core GEMM (mma.sync tf32), 64x64 block, high occupancy ----
// C[M,256] = diag(rscale?) * (A[M,K] @ B[256,K]^T) + bias  (opt relu)
// B is PRE-ROUNDED tf32. A rounded in-kernel iff CVTA.
// 128 threads (4 warps, 2x2), warp tile 32x32, BK=16, 6 CTAs/SM target.
template<bool RELU, bool CVTA>
__global__ void __launch_bounds__(128, 6)
gemm_mma64(const float* __restrict__ A, const float* __restrict__ B,
           const float* __restrict__ bias, float* __restrict__ C,
           const float* __restrict__ rscale, int M, int K) {
    __shared__ float As[2][64 * 20];
    __shared__ float Bs[2][64 * 20];

    const int tid = threadIdx.x;
    const int lane = tid & 31;
    const int wid = tid >> 5;
    const int wm = (wid & 1) * 32;
    const int wn = (wid >> 1) * 32;
    const int gid = lane >> 2;
    const int tig = lane & 3;
    const int bm = blockIdx.y * 64;
    const int bn = blockIdx.x * 64;

    float acc[2][4][4];
#pragma unroll
    for (int i = 0; i < 2; i++)
#pragma unroll
        for (int j = 0; j < 4; j++)
#pragma unroll
            for (int v = 0; v < 4; v++) acc[i][j][v] = 0.f;

    const int nIt = K >> 4;
    float4 pa[2], pb[2];

    // preload stage 0: A/B tiles are 64 rows x 16 cols = 256 float4, 2 per thread
#pragma unroll
    for (int u = 0; u < 2; u++) {
        int idx = tid + u * 128;
        int row = idx >> 2, c4 = idx & 3;
        pa[u] = make_float4(0.f, 0.f, 0.f, 0.f);
        if (bm + row < M)
            pa[u] = *reinterpret_cast<const float4*>(A + (size_t)(bm + row) * K + c4 * 4);
        pb[u] = *reinterpret_cast<const float4*>(B + (size_t)(bn + row) * K + c4 * 4);
    }
#pragma unroll
    for (int u = 0; u < 2; u++) {
        int idx = tid + u * 128;
        int row = idx >> 2, c4 = idx & 3;
        float4 va = pa[u];
        if (CVTA) { va.x = tf32_rn(va.x); va.y = tf32_rn(va.y); va.z = tf32_rn(va.z); va.w = tf32_rn(va.w); }
        *reinterpret_cast<float4*>(&As[0][row * 20 + c4 * 4]) = va;
        *reinterpret_cast<float4*>(&Bs[0][row * 20 + c4 * 4]) = pb[u];
    }
    __syncthreads();

    for (int it = 0; it < nIt; it++) {
        const int s = it & 1;
        const bool more = (it + 1) < nIt;
        if (more) {
            const int k0 = (it + 1) * 16;
#pragma unroll
            for (int u = 0; u < 2; u++) {
                int idx = tid + u * 128;
                int row = idx >> 2, c4 = idx & 3;
                pa[u] = make_float4(0.f, 0.f, 0.f, 0.f);
                if (bm + row < M)
                    pa[u] = *reinterpret_cast<const float4*>(A + (size_t)(bm + row) * K + k0 + c4 * 4);
                pb[u] = *reinterpret_cast<const float4*>(B + (size_t)(bn + row) * K + k0 + c4 * 4);
            }
        }
#pragma unroll
        for (int kk = 0; kk < 2; kk++) {
            const int kb = kk * 8;
            float a[2][4], b[4][2];
#pragma unroll
            for (int i = 0; i < 2; i++) {
                const float* p = &As[s][(wm + i * 16 + gid) * 20 + kb + tig];
                a[i][0] = p[0];
                a[i][1] = p[8 * 20];
                a[i][2] = p[4];
                a[i][3] = p[8 * 20 + 4];
            }
#pragma unroll
            for (int j = 0; j < 4; j++) {
                const float* p = &Bs[s][(wn + j * 8 + gid) * 20 + kb + tig];
                b[j][0] = p[0];
                b[j][1] = p[4];
            }
#pragma unroll
            for (int i = 0; i < 2; i++)
#pragma unroll
                for (int j = 0; j < 4; j++)
                    mma_tf32(acc[i][j], a[i], b[j]);
        }
        if (more) {
            const int ns = s ^ 1;
#pragma unroll
            for (int u = 0; u < 2; u++) {
                int idx = tid + u * 128;
                int row = idx >> 2, c4 = idx & 3;
                float4 va = pa[u];
                if (CVTA) { va.x = tf32_rn(va.x); va.y = tf32_rn(va.y); va.z = tf32_rn(va.z); va.w = tf32_rn(va.w); }
                *reinterpret_cast<float4*>(&As[ns][row * 20 + c4 * 4]) = va;
                *reinterpret_cast<float4*>(&Bs[ns][row * 20 + c4 * 4]) = pb[u];
            }
        }
        __syncthreads();
    }

#pragma unroll
    for (int j = 0; j < 4; j++) {
        const int col = bn + wn + j * 8 + tig * 2;
        const float bx = bias[col], by = bias[col + 1];
#pragma unroll
        for (int i = 0; i < 2; i++) {
            const int ra = bm + wm + i * 16 + gid;
            const int rb = ra + 8;
            if (ra < M) {
                float s = rscale ? rscale[ra] : 1.f;
                float2 v;
                v.x = acc[i][j][0] * s + bx;
                v.y = acc[i][j][1] * s + by;
                if (RELU) { v.x = fmaxf(v.x, 0.f); v.y = fmaxf(v.y, 0.f); }
                *reinterpret_cast<float2*>(C + (size_t)ra * HID + col) = v;
            }
            if (rb < M) {
                float s = rscale ? rscale[rb] : 1.f;
                float2 v;
                v.x = acc[i][j][2] * s + bx;
                v.y = acc[i][j][3] * s + by;
                if (RELU) { v.x = fmaxf(v.x, 0.f); v.y = fmaxf(v.y, 0.f); }
                *reinterpret_cast<float2*>(C + (size_t)rb * HID + col) = v;
            }
        }
    }
}

// ---------------- transpose gc2_weight [K,N] -> g_WT [N,K], tf32-rounded ----------------
__global__ void transpose_kernel(const float* __restrict__ W) {
    __shared__ float t[32][33];
    int bx = blockIdx.x * 32, by = blockIdx.y * 32;
    t[threadIdx.y][threadIdx.x] = W[(size_t)(by + threadIdx.y) * HID + bx + threadIdx.x];
    __syncthreads();
    g_WT[(size_t)(bx + threadIdx.y) * HID + by + threadIdx.x] = tf32_rn(t[threadIdx.x][threadIdx.y]);
}

__global__ void tail_kernel(const float* __restrict__ sw, float* __restrict__ out, int off) {
    if (threadIdx.x < 5) out[off + threadIdx.x] = sw[threadIdx.x];
}

// ---------------- launch ----------------
extern "C" void kernel_launch(void* const* d_in, const int* in_sizes, int n_in,
                              void* d_out, int out_size) {
    const float* feat0 = (const float*)d_in[0];
    const float* feat1 = (const float*)d_in[1];
    const float* feat2 = (const float*)d_in[2];
    const float* fc_w0 = (const float*)d_in[3];
    const float* fc_b0 = (const float*)d_in[4];
    const float* fc_w1 = (const float*)d_in[5];
    const float* fc_b1 = (const float*)d_in[6];
    const float* fc_w2 = (const float*)d_in[7];
    const float* fc_b2 = (const float*)d_in[8];
    const float* gc1_bias = (const float*)d_in[9];
    const float* gc2_weight = (const float*)d_in[10];
    const float* gc2_bias = (const float*)d_in[11];
    const float* semantic_weight = (const float*)d_in[12];
    const int* src = (const int*)d_in[13];   // JAX x64-disabled -> int32
    const int* dst = (const int*)d_in[14];
    float* out = (float*)d_out;

    float *H = nullptr, *AGG = nullptr, *WT = nullptr, *NI = nullptr;
    float *W0 = nullptr, *W1 = nullptr, *W2 = nullptr;
    void *DIN = nullptr, *DOUT = nullptr;
    cudaGetSymbolAddress((void**)&H, g_H);
    cudaGetSymbolAddress((void**)&AGG, g_AGG);
    cudaGetSymbolAddress((void**)&WT, g_WT);
    cudaGetSymbolAddress((void**)&NI, g_norm_in);
    cudaGetSymbolAddress((void**)&W0, g_W0);
    cudaGetSymbolAddress((void**)&W1, g_W1);
    cudaGetSymbolAddress((void**)&W2, g_W2);
    cudaGetSymbolAddress(&DIN, g_din);
    cudaGetSymbolAddress(&DOUT, g_dout);

    static cudaStream_t sPrep = nullptr;
    static cudaEvent_t evFork = nullptr, evJoin = nullptr;
    if (sPrep == nullptr) {
        cudaStreamCreateWithFlags(&sPrep, cudaStreamNonBlocking);
        cudaEventCreateWithFlags(&evFork, cudaEventDisableTiming);
        cudaEventCreateWithFlags(&evJoin, cudaEventDisableTiming);
    }

    cudaEventRecord(evFork, 0);
    cudaStreamWaitEvent(sPrep, evFork, 0);

    // ---- main stream: weight conversions then fc GEMMs (launch idx 5 = fc0, profiled) ----
    cvt_weights<<<(HID * 512 / 4 + 255) / 256, 256>>>(fc_w0, W0, HID * 512 / 4);   // 0
    cvt_weights<<<(HID * 256 / 4 + 255) / 256, 256>>>(fc_w1, W1, HID * 256 / 4);   // 1
    cvt_weights<<<(HID * 128 / 4 + 255) / 256, 256>>>(fc_w2, W2, HID * 128 / 4);   // 2
    gemm_mma64<false, true><<<dim3(4, (30000 + 63) / 64), 128>>>(                  // 3
        feat1, W1, fc_b1, H + (size_t)40000 * HID, nullptr, 30000, 256);
    gemm_mma64<false, true><<<dim3(4, (30000 + 63) / 64), 128>>>(                  // 4
        feat2, W2, fc_b2, H + (size_t)70000 * HID, nullptr, 30000, 128);
    gemm_mma64<false, true><<<dim3(4, (40000 + 63) / 64), 128>>>(                  // 5 <- profiled
        feat0, W0, fc_b0, H, nullptr, 40000, 512);

    // ---- prep stream: CSR build + norms + weight transpose ----
    cudaMemsetAsync(DIN, 0, N_NODES * sizeof(int), sPrep);
    cudaMemsetAsync(DOUT, 0, N_NODES * sizeof(int), sPrep);
    hist_kernel<<<(N_EDGES + 255) / 256, 256, 0, sPrep>>>(src, dst);
    scan_a<<<N_BLK, SCAN_B, 0, sPrep>>>();
    scan_c<<<(N_NODES + 255) / 256, 256, 0, sPrep>>>();
    scatter_kernel<<<(N_EDGES + 255) / 256, 256, 0, sPrep>>>(src, dst);
    transpose_kernel<<<dim3(8, 8), dim3(32, 32), 0, sPrep>>>(gc2_weight);
    cudaEventRecord(evJoin, sPrep);

    // ---- join, then graph layers ----
    cudaStreamWaitEvent(0, evJoin, 0);

    spmm_scaled<<<(N_NODES + 3) / 4, 256>>>(H, AGG, gc1_bias);
    spmm_plain<<<(N_NODES + 3) / 4, 256>>>(AGG, H);   // writes tf32-rounded H
    gemm_mma64<true, false><<<dim3(4, (N_NODES + 63) / 64), 128>>>(
        H, WT, gc2_bias, out, NI, N_NODES, 256);

    tail_kernel<<<1, 32>>>(semantic_weight, out, out_size - 5);
}

// round 12
// speedup vs baseline: 1.2664x; 1.2664x over previous
#include <cuda_runtime.h>
#include <cstdint>

#define N_NODES 100000
#define N_EDGES 300000
#define HID 256
#define SCAN_B 1024
#define N_BLK ((N_NODES + SCAN_B - 1) / SCAN_B)   // 98

// ---------------- scratch ----------------
__device__ float g_H[(size_t)N_NODES * HID];
__device__ float g_AGG[(size_t)N_NODES * HID];
__device__ float g_WT[HID * HID];       // gc2_weight^T, tf32-rounded
__device__ float g_W0[HID * 512];       // fc weights, tf32-rounded
__device__ float g_W1[HID * 256];
__device__ float g_W2[HID * 128];
__device__ float g_norm_out[N_NODES];
__device__ float g_norm_in[N_NODES];
__device__ int g_din[N_NODES];
__device__ int g_dout[N_NODES];
__device__ int g_row_ptr[N_NODES + 1];
__device__ int g_cursor[N_NODES];
__device__ int g_col[N_EDGES];
__device__ int g_blksum[N_BLK];

__device__ __forceinline__ float tf32_rn(float x) {
    uint32_t r;
    asm("cvt.rna.tf32.f32 %0, %1;" : "=r"(r) : "f"(x));
    return __uint_as_float(r);
}
__device__ __forceinline__ void mma_tf32(float* c, const float* a, const float* b) {
    asm volatile(
        "mma.sync.aligned.m16n8k8.row.col.f32.tf32.tf32.f32 "
        "{%0,%1,%2,%3}, {%4,%5,%6,%7}, {%8,%9}, {%0,%1,%2,%3};"
        : "+f"(c[0]), "+f"(c[1]), "+f"(c[2]), "+f"(c[3])
        : "r"(__float_as_uint(a[0])), "r"(__float_as_uint(a[1])),
          "r"(__float_as_uint(a[2])), "r"(__float_as_uint(a[3])),
          "r"(__float_as_uint(b[0])), "r"(__float_as_uint(b[1])));
}

// ---------------- weight pre-conversion (fp32 -> tf32-rounded fp32) ----------------
__global__ void cvt_weights(const float* __restrict__ W, float* __restrict__ out, int n4) {
    int i = blockIdx.x * blockDim.x + threadIdx.x;
    if (i < n4) {
        float4 v = reinterpret_cast<const float4*>(W)[i];
        v.x = tf32_rn(v.x); v.y = tf32_rn(v.y); v.z = tf32_rn(v.z); v.w = tf32_rn(v.w);
        reinterpret_cast<float4*>(out)[i] = v;
    }
}

// ---------------- CSR build ----------------
__global__ void hist_kernel(const int* __restrict__ src, const int* __restrict__ dst) {
    int e = blockIdx.x * blockDim.x + threadIdx.x;
    if (e < N_EDGES) {
        atomicAdd(&g_dout[src[e]], 1);
        atomicAdd(&g_din[dst[e]], 1);
    }
}
__global__ void scan_a() {
    __shared__ int sh[SCAN_B];
    int t = threadIdx.x, idx = blockIdx.x * SCAN_B + t;
    int v = (idx < N_NODES) ? g_din[idx] : 0;
    sh[t] = v;
    __syncthreads();
#pragma unroll
    for (int off = 1; off < SCAN_B; off <<= 1) {
        int add = (t >= off) ? sh[t - off] : 0;
        __syncthreads();
        sh[t] += add;
        __syncthreads();
    }
    if (idx < N_NODES) g_row_ptr[idx + 1] = sh[t];
    if (t == SCAN_B - 1) g_blksum[blockIdx.x] = sh[t];
}
__global__ void scan_c() {
    __shared__ int red[256];
    const int t = threadIdx.x;
    const int chunk = (blockIdx.x * 256) / SCAN_B;
    int part = 0;
    for (int i = t; i < chunk; i += 256) part += g_blksum[i];
    red[t] = part;
    __syncthreads();
#pragma unroll
    for (int o = 128; o > 0; o >>= 1) {
        if (t < o) red[t] += red[t + o];
        __syncthreads();
    }
    const int base = red[0];
    int idx = blockIdx.x * 256 + t;
    if (idx == 0) g_row_ptr[0] = 0;
    if (idx < N_NODES) {
        int inc = g_row_ptr[idx + 1] + base;
        g_row_ptr[idx + 1] = inc;
        g_cursor[idx] = inc - g_din[idx];
        g_norm_in[idx]  = rsqrtf(fmaxf((float)g_din[idx], 1.f));
        g_norm_out[idx] = rsqrtf(fmaxf((float)g_dout[idx], 1.f));
    }
}
__global__ void scatter_kernel(const int* __restrict__ src, const int* __restrict__ dst) {
    int e = blockIdx.x * blockDim.x + threadIdx.x;
    if (e < N_EDGES) {
        int pos = atomicAdd(&g_cursor[dst[e]], 1);
        g_col[pos] = src[e];
    }
}

// ---------------- CSR SpMM (layer 1): gather H[src]*norm_out[src], fused epilogue ----
__global__ void __launch_bounds__(256)
spmm_scaled(const float* __restrict__ X, float* __restrict__ out, const float* __restrict__ bias) {
    int node = blockIdx.x * 4 + (threadIdx.x >> 6);
    if (node >= N_NODES) return;
    int lane = threadIdx.x & 63;
    int beg = g_row_ptr[node], end = g_row_ptr[node + 1];
    float4 acc = make_float4(0.f, 0.f, 0.f, 0.f);
    int e = beg;
    for (; e + 2 <= end; e += 2) {
        int s0 = __ldg(&g_col[e]), s1 = __ldg(&g_col[e + 1]);
        float w0 = __ldg(&g_norm_out[s0]), w1 = __ldg(&g_norm_out[s1]);
        float4 v0 = __ldg(reinterpret_cast<const float4*>(X + (size_t)s0 * HID + lane * 4));
        float4 v1 = __ldg(reinterpret_cast<const float4*>(X + (size_t)s1 * HID + lane * 4));
        acc.x += v0.x * w0 + v1.x * w1;
        acc.y += v0.y * w0 + v1.y * w1;
        acc.z += v0.z * w0 + v1.z * w1;
        acc.w += v0.w * w0 + v1.w * w1;
    }
    if (e < end) {
        int s = __ldg(&g_col[e]);
        float w = __ldg(&g_norm_out[s]);
        float4 v = __ldg(reinterpret_cast<const float4*>(X + (size_t)s * HID + lane * 4));
        acc.x += v.x * w; acc.y += v.y * w; acc.z += v.z * w; acc.w += v.w * w;
    }
    float ni = g_norm_in[node];
    float no = g_norm_out[node];
    float4 b = *reinterpret_cast<const float4*>(bias + lane * 4);
    acc.x = fmaxf(acc.x * ni + b.x, 0.f) * no;
    acc.y = fmaxf(acc.y * ni + b.y, 0.f) * no;
    acc.z = fmaxf(acc.z * ni + b.z, 0.f) * no;
    acc.w = fmaxf(acc.w * ni + b.w, 0.f) * no;
    *reinterpret_cast<float4*>(out + (size_t)node * HID + lane * 4) = acc;
}

// ---------------- CSR SpMM (layer 2): plain gather-sum; output tf32-pre-rounded ----
__global__ void __launch_bounds__(256)
spmm_plain(const float* __restrict__ X, float* __restrict__ out) {
    int node = blockIdx.x * 4 + (threadIdx.x >> 6);
    if (node >= N_NODES) return;
    int lane = threadIdx.x & 63;
    int beg = g_row_ptr[node], end = g_row_ptr[node + 1];
    float4 acc = make_float4(0.f, 0.f, 0.f, 0.f);
    int e = beg;
    for (; e + 2 <= end; e += 2) {
        int s0 = __ldg(&g_col[e]), s1 = __ldg(&g_col[e + 1]);
        float4 v0 = __ldg(reinterpret_cast<const float4*>(X + (size_t)s0 * HID + lane * 4));
        float4 v1 = __ldg(reinterpret_cast<const float4*>(X + (size_t)s1 * HID + lane * 4));
        acc.x += v0.x + v1.x; acc.y += v0.y + v1.y;
        acc.z += v0.z + v1.z; acc.w += v0.w + v1.w;
    }
    if (e < end) {
        int s = __ldg(&g_col[e]);
        float4 v = __ldg(reinterpret_cast<const float4*>(X + (size_t)s * HID + lane * 4));
        acc.x += v.x; acc.y += v.y; acc.z += v.z; acc.w += v.w;
    }
    // pre-round for the consuming tf32 GEMM (CVTA=false path)
    acc.x = tf32_rn(acc.x); acc.y = tf32_rn(acc.y);
    acc.z = tf32_rn(acc.z); acc.w = tf32_rn(acc.w);
    *reinterpret_cast<float4*>(out + (size_t)node * HID + lane * 4) = acc;
}

// ---------------- tensor-core GEMM (mma.sync tf32), BN=128, 2 CTA/SM (R10 config) ----
// C[M,256] = diag(rscale?) * (A[M,K] @ B[256,K]^T) + bias  (opt relu)
// B is PRE-ROUNDED tf32. A rounded in-kernel iff CVTA.
template<bool RELU, bool CVTA>
__global__ void __launch_bounds__(256, 2)
gemm_mma(const float* __restrict__ A, const float* __restrict__ B,
         const float* __restrict__ bias, float* __restrict__ C,
         const float* __restrict__ rscale, int M, int K) {
    __shared__ float As[2][128 * 20];
    __shared__ float Bs[2][128 * 20];

    const int tid = threadIdx.x;
    const int lane = tid & 31;
    const int wid = tid >> 5;
    const int wm = (wid & 1) * 64;
    const int wn = (wid >> 1) * 32;
    const int gid = lane >> 2;
    const int tig = lane & 3;
    const int bm = blockIdx.y * 128;
    const int bn = blockIdx.x * 128;

    float acc[4][4][4];
#pragma unroll
    for (int i = 0; i < 4; i++)
#pragma unroll
        for (int j = 0; j < 4; j++)
#pragma unroll
            for (int v = 0; v < 4; v++) acc[i][j][v] = 0.f;

    const int nIt = K >> 4;
    float4 pa[2], pb[2];
#pragma unroll
    for (int u = 0; u < 2; u++) {
        int idx = tid + u * 256;
        int row = idx >> 2, c4 = idx & 3;
        pa[u] = make_float4(0.f, 0.f, 0.f, 0.f);
        if (bm + row < M)
            pa[u] = *reinterpret_cast<const float4*>(A + (size_t)(bm + row) * K + c4 * 4);
        pb[u] = *reinterpret_cast<const float4*>(B + (size_t)(bn + row) * K + c4 * 4);
    }
#pragma unroll
    for (int u = 0; u < 2; u++) {
        int idx = tid + u * 256;
        int row = idx >> 2, c4 = idx & 3;
        float4 va = pa[u];
        if (CVTA) { va.x = tf32_rn(va.x); va.y = tf32_rn(va.y); va.z = tf32_rn(va.z); va.w = tf32_rn(va.w); }
        *reinterpret_cast<float4*>(&As[0][row * 20 + c4 * 4]) = va;
        *reinterpret_cast<float4*>(&Bs[0][row * 20 + c4 * 4]) = pb[u];
    }
    __syncthreads();

    for (int it = 0; it < nIt; it++) {
        const int s = it & 1;
        const bool more = (it + 1) < nIt;
        if (more) {
            const int k0 = (it + 1) * 16;
#pragma unroll
            for (int u = 0; u < 2; u++) {
                int idx = tid + u * 256;
                int row = idx >> 2, c4 = idx & 3;
                pa[u] = make_float4(0.f, 0.f, 0.f, 0.f);
                if (bm + row < M)
                    pa[u] = *reinterpret_cast<const float4*>(A + (size_t)(bm + row) * K + k0 + c4 * 4);
                pb[u] = *reinterpret_cast<const float4*>(B + (size_t)(bn + row) * K + k0 + c4 * 4);
            }
        }
#pragma unroll
        for (int kk = 0; kk < 2; kk++) {
            const int kb = kk * 8;
            float a[4][4], b[4][2];
#pragma unroll
            for (int i = 0; i < 4; i++) {
                const float* p = &As[s][(wm + i * 16 + gid) * 20 + kb + tig];
                a[i][0] = p[0];
                a[i][1] = p[8 * 20];
                a[i][2] = p[4];
                a[i][3] = p[8 * 20 + 4];
            }
#pragma unroll
            for (int j = 0; j < 4; j++) {
                const float* p = &Bs[s][(wn + j * 8 + gid) * 20 + kb + tig];
                b[j][0] = p[0];
                b[j][1] = p[4];
            }
#pragma unroll
            for (int i = 0; i < 4; i++)
#pragma unroll
                for (int j = 0; j < 4; j++)
                    mma_tf32(acc[i][j], a[i], b[j]);
        }
        if (more) {
            const int ns = s ^ 1;
#pragma unroll
            for (int u = 0; u < 2; u++) {
                int idx = tid + u * 256;
                int row = idx >> 2, c4 = idx & 3;
                float4 va = pa[u];
                if (CVTA) { va.x = tf32_rn(va.x); va.y = tf32_rn(va.y); va.z = tf32_rn(va.z); va.w = tf32_rn(va.w); }
                *reinterpret_cast<float4*>(&As[ns][row * 20 + c4 * 4]) = va;
                *reinterpret_cast<float4*>(&Bs[ns][row * 20 + c4 * 4]) = pb[u];
            }
        }
        __syncthreads();
    }

#pragma unroll
    for (int j = 0; j < 4; j++) {
        const int col = bn + wn + j * 8 + tig * 2;
        const float bx = bias[col], by = bias[col + 1];
#pragma unroll
        for (int i = 0; i < 4; i++) {
            const int ra = bm + wm + i * 16 + gid;
            const int rb = ra + 8;
            if (ra < M) {
                float s = rscale ? rscale[ra] : 1.f;
                float2 v;
                v.x = acc[i][j][0] * s + bx;
                v.y = acc[i][j][1] * s + by;
                if (RELU) { v.x = fmaxf(v.x, 0.f); v.y = fmaxf(v.y, 0.f); }
                *reinterpret_cast<float2*>(C + (size_t)ra * HID + col) = v;
            }
            if (rb < M) {
                float s = rscale ? rscale[rb] : 1.f;
                float2 v;
                v.x = acc[i][j][2] * s + bx;
                v.y = acc[i][j][3] * s + by;
                if (RELU) { v.x = fmaxf(v.x, 0.f); v.y = fmaxf(v.y, 0.f); }
                *reinterpret_cast<float2*>(C + (size_t)rb * HID + col) = v;
            }
        }
    }
}

// ---------------- transpose gc2_weight [K,N] -> g_WT [N,K], tf32-rounded ----------------
__global__ void transpose_kernel(const float* __restrict__ W) {
    __shared__ float t[32][33];
    int bx = blockIdx.x * 32, by = blockIdx.y * 32;
    t[threadIdx.y][threadIdx.x] = W[(size_t)(by + threadIdx.y) * HID + bx + threadIdx.x];
    __syncthreads();
    g_WT[(size_t)(bx + threadIdx.y) * HID + by + threadIdx.x] = tf32_rn(t[threadIdx.x][threadIdx.y]);
}

__global__ void tail_kernel(const float* __restrict__ sw, float* __restrict__ out, int off) {
    if (threadIdx.x < 5) out[off + threadIdx.x] = sw[threadIdx.x];
}

// ---------------- launch ----------------
extern "C" void kernel_launch(void* const* d_in, const int* in_sizes, int n_in,
                              void* d_out, int out_size) {
    const float* feat0 = (const float*)d_in[0];
    const float* feat1 = (const float*)d_in[1];
    const float* feat2 = (const float*)d_in[2];
    const float* fc_w0 = (const float*)d_in[3];
    const float* fc_b0 = (const float*)d_in[4];
    const float* fc_w1 = (const float*)d_in[5];
    const float* fc_b1 = (const float*)d_in[6];
    const float* fc_w2 = (const float*)d_in[7];
    const float* fc_b2 = (const float*)d_in[8];
    const float* gc1_bias = (const float*)d_in[9];
    const float* gc2_weight = (const float*)d_in[10];
    const float* gc2_bias = (const float*)d_in[11];
    const float* semantic_weight = (const float*)d_in[12];
    const int* src = (const int*)d_in[13];   // JAX x64-disabled -> int32
    const int* dst = (const int*)d_in[14];
    float* out = (float*)d_out;

    float *H = nullptr, *AGG = nullptr, *WT = nullptr, *NI = nullptr;
    float *W0 = nullptr, *W1 = nullptr, *W2 = nullptr;
    void *DIN = nullptr, *DOUT = nullptr;
    cudaGetSymbolAddress((void**)&H, g_H);
    cudaGetSymbolAddress((void**)&AGG, g_AGG);
    cudaGetSymbolAddress((void**)&WT, g_WT);
    cudaGetSymbolAddress((void**)&NI, g_norm_in);
    cudaGetSymbolAddress((void**)&W0, g_W0);
    cudaGetSymbolAddress((void**)&W1, g_W1);
    cudaGetSymbolAddress((void**)&W2, g_W2);
    cudaGetSymbolAddress(&DIN, g_din);
    cudaGetSymbolAddress(&DOUT, g_dout);

    // streams/events created once on first (uncaptured) call — pure launch infra
    static cudaStream_t sPrep = nullptr, s1 = nullptr, s2 = nullptr;
    static cudaEvent_t evFork = nullptr, evJoin = nullptr, ev1 = nullptr, ev2 = nullptr;
    if (sPrep == nullptr) {
        cudaStreamCreateWithFlags(&sPrep, cudaStreamNonBlocking);
        cudaStreamCreateWithFlags(&s1, cudaStreamNonBlocking);
        cudaStreamCreateWithFlags(&s2, cudaStreamNonBlocking);
        cudaEventCreateWithFlags(&evFork, cudaEventDisableTiming);
        cudaEventCreateWithFlags(&evJoin, cudaEventDisableTiming);
        cudaEventCreateWithFlags(&ev1, cudaEventDisableTiming);
        cudaEventCreateWithFlags(&ev2, cudaEventDisableTiming);
    }

    cudaEventRecord(evFork, 0);
    cudaStreamWaitEvent(sPrep, evFork, 0);
    cudaStreamWaitEvent(s1, evFork, 0);
    cudaStreamWaitEvent(s2, evFork, 0);

    // ---- s1: fc1 branch ----
    cvt_weights<<<(HID * 256 / 4 + 255) / 256, 256, 0, s1>>>(fc_w1, W1, HID * 256 / 4);
    gemm_mma<false, true><<<dim3(2, (30000 + 127) / 128), 256, 0, s1>>>(
        feat1, W1, fc_b1, H + (size_t)40000 * HID, nullptr, 30000, 256);
    cudaEventRecord(ev1, s1);

    // ---- s2: fc2 branch ----
    cvt_weights<<<(HID * 128 / 4 + 255) / 256, 256, 0, s2>>>(fc_w2, W2, HID * 128 / 4);
    gemm_mma<false, true><<<dim3(2, (30000 + 127) / 128), 256, 0, s2>>>(
        feat2, W2, fc_b2, H + (size_t)70000 * HID, nullptr, 30000, 128);
    cudaEventRecord(ev2, s2);

    // ---- main: fc0 branch (concurrent with s1/s2) ----
    cvt_weights<<<(HID * 512 / 4 + 255) / 256, 256>>>(fc_w0, W0, HID * 512 / 4);
    gemm_mma<false, true><<<dim3(2, (40000 + 127) / 128), 256>>>(
        feat0, W0, fc_b0, H, nullptr, 40000, 512);

    // ---- prep stream: CSR build + norms + weight transpose ----
    cudaMemsetAsync(DIN, 0, N_NODES * sizeof(int), sPrep);
    cudaMemsetAsync(DOUT, 0, N_NODES * sizeof(int), sPrep);
    hist_kernel<<<(N_EDGES + 255) / 256, 256, 0, sPrep>>>(src, dst);
    scan_a<<<N_BLK, SCAN_B, 0, sPrep>>>();
    scan_c<<<(N_NODES + 255) / 256, 256, 0, sPrep>>>();
    scatter_kernel<<<(N_EDGES + 255) / 256, 256, 0, sPrep>>>(src, dst);
    transpose_kernel<<<dim3(8, 8), dim3(32, 32), 0, sPrep>>>(gc2_weight);
    cudaEventRecord(evJoin, sPrep);

    // ---- join all branches on main ----
    cudaStreamWaitEvent(0, ev1, 0);
    cudaStreamWaitEvent(0, ev2, 0);
    cudaStreamWaitEvent(0, evJoin, 0);

    spmm_scaled<<<(N_NODES + 3) / 4, 256>>>(H, AGG, gc1_bias);
    spmm_plain<<<(N_NODES + 3) / 4, 256>>>(AGG, H);   // writes tf32-rounded H
    gemm_mma<true, false><<<dim3(2, (N_NODES + 127) / 128), 256>>>(
        H, WT, gc2_bias, out, NI, N_NODES, 256);

    tail_kernel<<<1, 32>>>(semantic_weight, out, out_size - 5);
}

// round 13
// speedup vs baseline: 1.4319x; 1.1307x over previous
#include <cuda_runtime.h>
#include <cstdint>

#define N_NODES 100000
#define N_EDGES 300000
#define HID 256
#define SCAN_B 1024
#define N_BLK ((N_NODES + SCAN_B - 1) / SCAN_B)   // 98

// GEMM pipeline config
#define STAGE_F 2560                 // floats per stage per matrix (128 rows * 20)
#define GEMM_SMEM_BYTES (3 * STAGE_F * 2 * 4)   // 61440

// ---------------- scratch ----------------
__device__ float g_H[(size_t)N_NODES * HID];
__device__ float g_AGG[(size_t)N_NODES * HID];
__device__ float g_WT[HID * HID];       // gc2_weight^T, tf32-rounded
__device__ float g_W0[HID * 512];       // fc weights, tf32-rounded
__device__ float g_W1[HID * 256];
__device__ float g_W2[HID * 128];
__device__ float g_norm_out[N_NODES];
__device__ float g_norm_in[N_NODES];
__device__ int g_din[N_NODES];
__device__ int g_dout[N_NODES];
__device__ int g_row_ptr[N_NODES + 1];
__device__ int g_cursor[N_NODES];
__device__ int g_col[N_EDGES];
__device__ int g_blksum[N_BLK];

__device__ __forceinline__ float tf32_rn(float x) {
    uint32_t r;
    asm("cvt.rna.tf32.f32 %0, %1;" : "=r"(r) : "f"(x));
    return __uint_as_float(r);
}
__device__ __forceinline__ void mma_tf32(float* c, const float* a, const float* b) {
    asm volatile(
        "mma.sync.aligned.m16n8k8.row.col.f32.tf32.tf32.f32 "
        "{%0,%1,%2,%3}, {%4,%5,%6,%7}, {%8,%9}, {%0,%1,%2,%3};"
        : "+f"(c[0]), "+f"(c[1]), "+f"(c[2]), "+f"(c[3])
        : "r"(__float_as_uint(a[0])), "r"(__float_as_uint(a[1])),
          "r"(__float_as_uint(a[2])), "r"(__float_as_uint(a[3])),
          "r"(__float_as_uint(b[0])), "r"(__float_as_uint(b[1])));
}

// ---------------- weight pre-conversion (fp32 -> tf32-rounded fp32) ----------------
__global__ void cvt_weights(const float* __restrict__ W, float* __restrict__ out, int n4) {
    int i = blockIdx.x * blockDim.x + threadIdx.x;
    if (i < n4) {
        float4 v = reinterpret_cast<const float4*>(W)[i];
        v.x = tf32_rn(v.x); v.y = tf32_rn(v.y); v.z = tf32_rn(v.z); v.w = tf32_rn(v.w);
        reinterpret_cast<float4*>(out)[i] = v;
    }
}

// ---------------- CSR build ----------------
__global__ void hist_kernel(const int* __restrict__ src, const int* __restrict__ dst) {
    int e = blockIdx.x * blockDim.x + threadIdx.x;
    if (e < N_EDGES) {
        atomicAdd(&g_dout[src[e]], 1);
        atomicAdd(&g_din[dst[e]], 1);
    }
}
__global__ void scan_a() {
    __shared__ int sh[SCAN_B];
    int t = threadIdx.x, idx = blockIdx.x * SCAN_B + t;
    int v = (idx < N_NODES) ? g_din[idx] : 0;
    sh[t] = v;
    __syncthreads();
#pragma unroll
    for (int off = 1; off < SCAN_B; off <<= 1) {
        int add = (t >= off) ? sh[t - off] : 0;
        __syncthreads();
        sh[t] += add;
        __syncthreads();
    }
    if (idx < N_NODES) g_row_ptr[idx + 1] = sh[t];
    if (t == SCAN_B - 1) g_blksum[blockIdx.x] = sh[t];
}
__global__ void scan_c() {
    __shared__ int red[256];
    const int t = threadIdx.x;
    const int chunk = (blockIdx.x * 256) / SCAN_B;
    int part = 0;
    for (int i = t; i < chunk; i += 256) part += g_blksum[i];
    red[t] = part;
    __syncthreads();
#pragma unroll
    for (int o = 128; o > 0; o >>= 1) {
        if (t < o) red[t] += red[t + o];
        __syncthreads();
    }
    const int base = red[0];
    int idx = blockIdx.x * 256 + t;
    if (idx == 0) g_row_ptr[0] = 0;
    if (idx < N_NODES) {
        int inc = g_row_ptr[idx + 1] + base;
        g_row_ptr[idx + 1] = inc;
        g_cursor[idx] = inc - g_din[idx];
        g_norm_in[idx]  = rsqrtf(fmaxf((float)g_din[idx], 1.f));
        g_norm_out[idx] = rsqrtf(fmaxf((float)g_dout[idx], 1.f));
    }
}
__global__ void scatter_kernel(const int* __restrict__ src, const int* __restrict__ dst) {
    int e = blockIdx.x * blockDim.x + threadIdx.x;
    if (e < N_EDGES) {
        int pos = atomicAdd(&g_cursor[dst[e]], 1);
        g_col[pos] = src[e];
    }
}

// ---------------- CSR SpMM (layer 1): gather H[src]*norm_out[src], fused epilogue ----
__global__ void __launch_bounds__(256)
spmm_scaled(const float* __restrict__ X, float* __restrict__ out, const float* __restrict__ bias) {
    int node = blockIdx.x * 4 + (threadIdx.x >> 6);
    if (node >= N_NODES) return;
    int lane = threadIdx.x & 63;
    int beg = g_row_ptr[node], end = g_row_ptr[node + 1];
    float4 acc = make_float4(0.f, 0.f, 0.f, 0.f);
    int e = beg;
    for (; e + 2 <= end; e += 2) {
        int s0 = __ldg(&g_col[e]), s1 = __ldg(&g_col[e + 1]);
        float w0 = __ldg(&g_norm_out[s0]), w1 = __ldg(&g_norm_out[s1]);
        float4 v0 = __ldg(reinterpret_cast<const float4*>(X + (size_t)s0 * HID + lane * 4));
        float4 v1 = __ldg(reinterpret_cast<const float4*>(X + (size_t)s1 * HID + lane * 4));
        acc.x += v0.x * w0 + v1.x * w1;
        acc.y += v0.y * w0 + v1.y * w1;
        acc.z += v0.z * w0 + v1.z * w1;
        acc.w += v0.w * w0 + v1.w * w1;
    }
    if (e < end) {
        int s = __ldg(&g_col[e]);
        float w = __ldg(&g_norm_out[s]);
        float4 v = __ldg(reinterpret_cast<const float4*>(X + (size_t)s * HID + lane * 4));
        acc.x += v.x * w; acc.y += v.y * w; acc.z += v.z * w; acc.w += v.w * w;
    }
    float ni = g_norm_in[node];
    float no = g_norm_out[node];
    float4 b = *reinterpret_cast<const float4*>(bias + lane * 4);
    acc.x = fmaxf(acc.x * ni + b.x, 0.f) * no;
    acc.y = fmaxf(acc.y * ni + b.y, 0.f) * no;
    acc.z = fmaxf(acc.z * ni + b.z, 0.f) * no;
    acc.w = fmaxf(acc.w * ni + b.w, 0.f) * no;
    *reinterpret_cast<float4*>(out + (size_t)node * HID + lane * 4) = acc;
}

// ---------------- CSR SpMM (layer 2): plain gather-sum; output tf32-pre-rounded ----
__global__ void __launch_bounds__(256)
spmm_plain(const float* __restrict__ X, float* __restrict__ out) {
    int node = blockIdx.x * 4 + (threadIdx.x >> 6);
    if (node >= N_NODES) return;
    int lane = threadIdx.x & 63;
    int beg = g_row_ptr[node], end = g_row_ptr[node + 1];
    float4 acc = make_float4(0.f, 0.f, 0.f, 0.f);
    int e = beg;
    for (; e + 2 <= end; e += 2) {
        int s0 = __ldg(&g_col[e]), s1 = __ldg(&g_col[e + 1]);
        float4 v0 = __ldg(reinterpret_cast<const float4*>(X + (size_t)s0 * HID + lane * 4));
        float4 v1 = __ldg(reinterpret_cast<const float4*>(X + (size_t)s1 * HID + lane * 4));
        acc.x += v0.x + v1.x; acc.y += v0.y + v1.y;
        acc.z += v0.z + v1.z; acc.w += v0.w + v1.w;
    }
    if (e < end) {
        int s = __ldg(&g_col[e]);
        float4 v = __ldg(reinterpret_cast<const float4*>(X + (size_t)s * HID + lane * 4));
        acc.x += v.x; acc.y += v.y; acc.z += v.z; acc.w += v.w;
    }
    acc.x = tf32_rn(acc.x); acc.y = tf32_rn(acc.y);
    acc.z = tf32_rn(acc.z); acc.w = tf32_rn(acc.w);
    *reinterpret_cast<float4*>(out + (size_t)node * HID + lane * 4) = acc;
}

// ---------------- tensor-core GEMM: cp.async 3-stage pipeline ----------------
// C[M,256] = diag(rscale?) * (A[M,K] @ B[256,K]^T) + bias  (opt relu)
// B PRE-ROUNDED tf32. A fragments rounded post-LDS iff CVTA.
template<bool RELU, bool CVTA>
__global__ void __launch_bounds__(256, 2)
gemm_cp(const float* __restrict__ A, const float* __restrict__ B,
        const float* __restrict__ bias, float* __restrict__ C,
        const float* __restrict__ rscale, int M, int K) {
    extern __shared__ float sm[];   // [3 stages A][3 stages B], each 2560 floats
    const uint32_t smem_base = (uint32_t)__cvta_generic_to_shared(sm);

    const int tid = threadIdx.x;
    const int lane = tid & 31;
    const int wid = tid >> 5;
    const int wm = (wid & 1) * 64;
    const int wn = (wid >> 1) * 32;
    const int gid = lane >> 2;
    const int tig = lane & 3;
    const int bm = blockIdx.y * 128;
    const int bn = blockIdx.x * 128;

    // per-thread copy coordinates (2 slots, 512 float4 per tile)
    const int r0 = tid >> 2, r1 = (tid + 256) >> 2;
    const int c40 = (tid & 3) * 4, c41 = c40;   // same c4 for both slots (idx&3 identical)
    const int ga0 = bm + r0, ga1 = bm + r1;
    const float* a_src0 = A + (size_t)(ga0 < M ? ga0 : (M - 1)) * K + c40;
    const float* a_src1 = A + (size_t)(ga1 < M ? ga1 : (M - 1)) * K + c41;
    const int asz0 = (ga0 < M) ? 16 : 0;
    const int asz1 = (ga1 < M) ? 16 : 0;
    const float* b_src0 = B + (size_t)(bn + r0) * K + c40;
    const float* b_src1 = B + (size_t)(bn + r1) * K + c41;
    const uint32_t a_off0 = (uint32_t)((r0 * 20 + c40) * 4);
    const uint32_t a_off1 = (uint32_t)((r1 * 20 + c41) * 4);

    auto issue_stage = [&](int st, int k0) {
        uint32_t abase = smem_base + (uint32_t)(st * STAGE_F * 4);
        uint32_t bbase = smem_base + (uint32_t)((3 + st) * STAGE_F * 4);
        asm volatile("cp.async.cg.shared.global [%0], [%1], 16, %2;"
                     :: "r"(abase + a_off0), "l"(a_src0 + k0), "r"(asz0));
        asm volatile("cp.async.cg.shared.global [%0], [%1], 16, %2;"
                     :: "r"(abase + a_off1), "l"(a_src1 + k0), "r"(asz1));
        asm volatile("cp.async.cg.shared.global [%0], [%1], 16;"
                     :: "r"(bbase + a_off0), "l"(b_src0 + k0));
        asm volatile("cp.async.cg.shared.global [%0], [%1], 16;"
                     :: "r"(bbase + a_off1), "l"(b_src1 + k0));
        asm volatile("cp.async.commit_group;");
    };

    float acc[4][4][4];
#pragma unroll
    for (int i = 0; i < 4; i++)
#pragma unroll
        for (int j = 0; j < 4; j++)
#pragma unroll
            for (int v = 0; v < 4; v++) acc[i][j][v] = 0.f;

    const int nIt = K >> 4;

    issue_stage(0, 0);
    issue_stage(1, 16);
    asm volatile("cp.async.wait_group 1;");
    __syncthreads();

    for (int it = 0; it < nIt; it++) {
        const int s = it % 3;
        const float* As = sm + s * STAGE_F;
        const float* Bs = sm + (3 + s) * STAGE_F;

#pragma unroll
        for (int kk = 0; kk < 2; kk++) {
            const int kb = kk * 8;
            float a[4][4], b[4][2];
#pragma unroll
            for (int i = 0; i < 4; i++) {
                const float* p = &As[(wm + i * 16 + gid) * 20 + kb + tig];
                a[i][0] = p[0];
                a[i][1] = p[8 * 20];
                a[i][2] = p[4];
                a[i][3] = p[8 * 20 + 4];
                if (CVTA) {
                    a[i][0] = tf32_rn(a[i][0]); a[i][1] = tf32_rn(a[i][1]);
                    a[i][2] = tf32_rn(a[i][2]); a[i][3] = tf32_rn(a[i][3]);
                }
            }
#pragma unroll
            for (int j = 0; j < 4; j++) {
                const float* p = &Bs[(wn + j * 8 + gid) * 20 + kb + tig];
                b[j][0] = p[0];
                b[j][1] = p[4];
            }
#pragma unroll
            for (int i = 0; i < 4; i++)
#pragma unroll
                for (int j = 0; j < 4; j++)
                    mma_tf32(acc[i][j], a[i], b[j]);
        }

        const int nx = it + 2;
        if (nx < nIt) issue_stage(nx % 3, nx * 16);
        else asm volatile("cp.async.commit_group;");   // empty group keeps count aligned
        asm volatile("cp.async.wait_group 1;");
        __syncthreads();
    }

#pragma unroll
    for (int j = 0; j < 4; j++) {
        const int col = bn + wn + j * 8 + tig * 2;
        const float bx = bias[col], by = bias[col + 1];
#pragma unroll
        for (int i = 0; i < 4; i++) {
            const int ra = bm + wm + i * 16 + gid;
            const int rb = ra + 8;
            if (ra < M) {
                float s = rscale ? rscale[ra] : 1.f;
                float2 v;
                v.x = acc[i][j][0] * s + bx;
                v.y = acc[i][j][1] * s + by;
                if (RELU) { v.x = fmaxf(v.x, 0.f); v.y = fmaxf(v.y, 0.f); }
                *reinterpret_cast<float2*>(C + (size_t)ra * HID + col) = v;
            }
            if (rb < M) {
                float s = rscale ? rscale[rb] : 1.f;
                float2 v;
                v.x = acc[i][j][2] * s + bx;
                v.y = acc[i][j][3] * s + by;
                if (RELU) { v.x = fmaxf(v.x, 0.f); v.y = fmaxf(v.y, 0.f); }
                *reinterpret_cast<float2*>(C + (size_t)rb * HID + col) = v;
            }
        }
    }
}

// ---------------- transpose gc2_weight [K,N] -> g_WT [N,K], tf32-rounded ----------------
__global__ void transpose_kernel(const float* __restrict__ W) {
    __shared__ float t[32][33];
    int bx = blockIdx.x * 32, by = blockIdx.y * 32;
    t[threadIdx.y][threadIdx.x] = W[(size_t)(by + threadIdx.y) * HID + bx + threadIdx.x];
    __syncthreads();
    g_WT[(size_t)(bx + threadIdx.y) * HID + by + threadIdx.x] = tf32_rn(t[threadIdx.x][threadIdx.y]);
}

__global__ void tail_kernel(const float* __restrict__ sw, float* __restrict__ out, int off) {
    if (threadIdx.x < 5) out[off + threadIdx.x] = sw[threadIdx.x];
}

// ---------------- launch ----------------
extern "C" void kernel_launch(void* const* d_in, const int* in_sizes, int n_in,
                              void* d_out, int out_size) {
    const float* feat0 = (const float*)d_in[0];
    const float* feat1 = (const float*)d_in[1];
    const float* feat2 = (const float*)d_in[2];
    const float* fc_w0 = (const float*)d_in[3];
    const float* fc_b0 = (const float*)d_in[4];
    const float* fc_w1 = (const float*)d_in[5];
    const float* fc_b1 = (const float*)d_in[6];
    const float* fc_w2 = (const float*)d_in[7];
    const float* fc_b2 = (const float*)d_in[8];
    const float* gc1_bias = (const float*)d_in[9];
    const float* gc2_weight = (const float*)d_in[10];
    const float* gc2_bias = (const float*)d_in[11];
    const float* semantic_weight = (const float*)d_in[12];
    const int* src = (const int*)d_in[13];   // JAX x64-disabled -> int32
    const int* dst = (const int*)d_in[14];
    float* out = (float*)d_out;

    float *H = nullptr, *AGG = nullptr, *WT = nullptr, *NI = nullptr;
    float *W0 = nullptr, *W1 = nullptr, *W2 = nullptr;
    void *DIN = nullptr, *DOUT = nullptr;
    cudaGetSymbolAddress((void**)&H, g_H);
    cudaGetSymbolAddress((void**)&AGG, g_AGG);
    cudaGetSymbolAddress((void**)&WT, g_WT);
    cudaGetSymbolAddress((void**)&NI, g_norm_in);
    cudaGetSymbolAddress((void**)&W0, g_W0);
    cudaGetSymbolAddress((void**)&W1, g_W1);
    cudaGetSymbolAddress((void**)&W2, g_W2);
    cudaGetSymbolAddress(&DIN, g_din);
    cudaGetSymbolAddress(&DOUT, g_dout);

    static cudaStream_t sPrep = nullptr, s1 = nullptr, s2 = nullptr;
    static cudaEvent_t evFork = nullptr, evJoin = nullptr, ev1 = nullptr, ev2 = nullptr;
    if (sPrep == nullptr) {
        cudaStreamCreateWithFlags(&sPrep, cudaStreamNonBlocking);
        cudaStreamCreateWithFlags(&s1, cudaStreamNonBlocking);
        cudaStreamCreateWithFlags(&s2, cudaStreamNonBlocking);
        cudaEventCreateWithFlags(&evFork, cudaEventDisableTiming);
        cudaEventCreateWithFlags(&evJoin, cudaEventDisableTiming);
        cudaEventCreateWithFlags(&ev1, cudaEventDisableTiming);
        cudaEventCreateWithFlags(&ev2, cudaEventDisableTiming);
        cudaFuncSetAttribute(gemm_cp<false, true>, cudaFuncAttributeMaxDynamicSharedMemorySize, GEMM_SMEM_BYTES);
        cudaFuncSetAttribute(gemm_cp<true, false>, cudaFuncAttributeMaxDynamicSharedMemorySize, GEMM_SMEM_BYTES);
    }

    cudaEventRecord(evFork, 0);
    cudaStreamWaitEvent(sPrep, evFork, 0);
    cudaStreamWaitEvent(s1, evFork, 0);
    cudaStreamWaitEvent(s2, evFork, 0);

    // ---- s1: fc1 branch ----
    cvt_weights<<<(HID * 256 / 4 + 255) / 256, 256, 0, s1>>>(fc_w1, W1, HID * 256 / 4);
    gemm_cp<false, true><<<dim3(2, (30000 + 127) / 128), 256, GEMM_SMEM_BYTES, s1>>>(
        feat1, W1, fc_b1, H + (size_t)40000 * HID, nullptr, 30000, 256);
    cudaEventRecord(ev1, s1);

    // ---- s2: fc2 branch ----
    cvt_weights<<<(HID * 128 / 4 + 255) / 256, 256, 0, s2>>>(fc_w2, W2, HID * 128 / 4);
    gemm_cp<false, true><<<dim3(2, (30000 + 127) / 128), 256, GEMM_SMEM_BYTES, s2>>>(
        feat2, W2, fc_b2, H + (size_t)70000 * HID, nullptr, 30000, 128);
    cudaEventRecord(ev2, s2);

    // ---- main: fc0 branch (concurrent with s1/s2) ----
    cvt_weights<<<(HID * 512 / 4 + 255) / 256, 256>>>(fc_w0, W0, HID * 512 / 4);
    gemm_cp<false, true><<<dim3(2, (40000 + 127) / 128), 256, GEMM_SMEM_BYTES>>>(
        feat0, W0, fc_b0, H, nullptr, 40000, 512);

    // ---- prep stream: CSR build + norms + weight transpose ----
    cudaMemsetAsync(DIN, 0, N_NODES * sizeof(int), sPrep);
    cudaMemsetAsync(DOUT, 0, N_NODES * sizeof(int), sPrep);
    hist_kernel<<<(N_EDGES + 255) / 256, 256, 0, sPrep>>>(src, dst);
    scan_a<<<N_BLK, SCAN_B, 0, sPrep>>>();
    scan_c<<<(N_NODES + 255) / 256, 256, 0, sPrep>>>();
    scatter_kernel<<<(N_EDGES + 255) / 256, 256, 0, sPrep>>>(src, dst);
    transpose_kernel<<<dim3(8, 8), dim3(32, 32), 0, sPrep>>>(gc2_weight);
    cudaEventRecord(evJoin, sPrep);

    // ---- join all branches on main ----
    cudaStreamWaitEvent(0, ev1, 0);
    cudaStreamWaitEvent(0, ev2, 0);
    cudaStreamWaitEvent(0, evJoin, 0);

    spmm_scaled<<<(N_NODES + 3) / 4, 256>>>(H, AGG, gc1_bias);
    spmm_plain<<<(N_NODES + 3) / 4, 256>>>(AGG, H);   // writes tf32-rounded H
    gemm_cp<true, false><<<dim3(2, (N_NODES + 127) / 128), 256, GEMM_SMEM_BYTES>>>(
        H, WT, gc2_bias, out, NI, N_NODES, 256);

    tail_kernel<<<1, 32>>>(semantic_weight, out, out_size - 5);
}

// round 14
// speedup vs baseline: 1.4509x; 1.0133x over previous
#include <cuda_runtime.h>
#include <cstdint>

#define N_NODES 100000
#define N_EDGES 300000
#define HID 256
#define SCAN_B 1024
#define N_BLK ((N_NODES + SCAN_B - 1) / SCAN_B)   // 98

// GEMM pipeline config: 4 stages
#define STAGE_F 2560                               // floats per stage per matrix (128*20)
#define GEMM_STAGES 4
#define GEMM_SMEM_BYTES (GEMM_STAGES * STAGE_F * 2 * 4)   // 81920

// spmm_plain / gc2 chunking (tile-aligned split)
#define CHUNK0 50048

// ---------------- scratch ----------------
__device__ float g_H[(size_t)N_NODES * HID];
__device__ float g_AGG[(size_t)N_NODES * HID];
__device__ float g_WT[HID * HID];       // gc2_weight^T, tf32-rounded
__device__ float g_W0[HID * 512];       // fc weights, tf32-rounded
__device__ float g_W1[HID * 256];
__device__ float g_W2[HID * 128];
__device__ float g_norm_out[N_NODES];
__device__ float g_norm_in[N_NODES];
__device__ int g_din[N_NODES];
__device__ int g_dout[N_NODES];
__device__ int g_row_ptr[N_NODES + 1];
__device__ int g_cursor[N_NODES];
__device__ int g_col[N_EDGES];
__device__ int g_blksum[N_BLK];

__device__ __forceinline__ float tf32_rn(float x) {
    uint32_t r;
    asm("cvt.rna.tf32.f32 %0, %1;" : "=r"(r) : "f"(x));
    return __uint_as_float(r);
}
__device__ __forceinline__ void mma_tf32(float* c, const float* a, const float* b) {
    asm volatile(
        "mma.sync.aligned.m16n8k8.row.col.f32.tf32.tf32.f32 "
        "{%0,%1,%2,%3}, {%4,%5,%6,%7}, {%8,%9}, {%0,%1,%2,%3};"
        : "+f"(c[0]), "+f"(c[1]), "+f"(c[2]), "+f"(c[3])
        : "r"(__float_as_uint(a[0])), "r"(__float_as_uint(a[1])),
          "r"(__float_as_uint(a[2])), "r"(__float_as_uint(a[3])),
          "r"(__float_as_uint(b[0])), "r"(__float_as_uint(b[1])));
}

// ---------------- weight pre-conversion ----------------
__global__ void cvt_weights(const float* __restrict__ W, float* __restrict__ out, int n4) {
    int i = blockIdx.x * blockDim.x + threadIdx.x;
    if (i < n4) {
        float4 v = reinterpret_cast<const float4*>(W)[i];
        v.x = tf32_rn(v.x); v.y = tf32_rn(v.y); v.z = tf32_rn(v.z); v.w = tf32_rn(v.w);
        reinterpret_cast<float4*>(out)[i] = v;
    }
}

// ---------------- CSR build ----------------
__global__ void hist_kernel(const int* __restrict__ src, const int* __restrict__ dst) {
    int e = blockIdx.x * blockDim.x + threadIdx.x;
    if (e < N_EDGES) {
        atomicAdd(&g_dout[src[e]], 1);
        atomicAdd(&g_din[dst[e]], 1);
    }
}
__global__ void scan_a() {
    __shared__ int sh[SCAN_B];
    int t = threadIdx.x, idx = blockIdx.x * SCAN_B + t;
    int v = (idx < N_NODES) ? g_din[idx] : 0;
    sh[t] = v;
    __syncthreads();
#pragma unroll
    for (int off = 1; off < SCAN_B; off <<= 1) {
        int add = (t >= off) ? sh[t - off] : 0;
        __syncthreads();
        sh[t] += add;
        __syncthreads();
    }
    if (idx < N_NODES) g_row_ptr[idx + 1] = sh[t];
    if (t == SCAN_B - 1) g_blksum[blockIdx.x] = sh[t];
}
__global__ void scan_c() {
    __shared__ int red[256];
    const int t = threadIdx.x;
    const int chunk = (blockIdx.x * 256) / SCAN_B;
    int part = 0;
    for (int i = t; i < chunk; i += 256) part += g_blksum[i];
    red[t] = part;
    __syncthreads();
#pragma unroll
    for (int o = 128; o > 0; o >>= 1) {
        if (t < o) red[t] += red[t + o];
        __syncthreads();
    }
    const int base = red[0];
    int idx = blockIdx.x * 256 + t;
    if (idx == 0) g_row_ptr[0] = 0;
    if (idx < N_NODES) {
        int inc = g_row_ptr[idx + 1] + base;
        g_row_ptr[idx + 1] = inc;
        g_cursor[idx] = inc - g_din[idx];
        g_norm_in[idx]  = rsqrtf(fmaxf((float)g_din[idx], 1.f));
        g_norm_out[idx] = rsqrtf(fmaxf((float)g_dout[idx], 1.f));
    }
}
__global__ void scatter_kernel(const int* __restrict__ src, const int* __restrict__ dst) {
    int e = blockIdx.x * blockDim.x + threadIdx.x;
    if (e < N_EDGES) {
        int pos = atomicAdd(&g_cursor[dst[e]], 1);
        g_col[pos] = src[e];
    }
}

// ---------------- CSR SpMM (layer 1): gather H[src]*norm_out[src], fused epilogue ----
__global__ void __launch_bounds__(256)
spmm_scaled(const float* __restrict__ X, float* __restrict__ out, const float* __restrict__ bias) {
    int node = blockIdx.x * 4 + (threadIdx.x >> 6);
    if (node >= N_NODES) return;
    int lane = threadIdx.x & 63;
    int beg = g_row_ptr[node], end = g_row_ptr[node + 1];
    float4 acc = make_float4(0.f, 0.f, 0.f, 0.f);
    int e = beg;
    for (; e + 2 <= end; e += 2) {
        int s0 = __ldg(&g_col[e]), s1 = __ldg(&g_col[e + 1]);
        float w0 = __ldg(&g_norm_out[s0]), w1 = __ldg(&g_norm_out[s1]);
        float4 v0 = __ldg(reinterpret_cast<const float4*>(X + (size_t)s0 * HID + lane * 4));
        float4 v1 = __ldg(reinterpret_cast<const float4*>(X + (size_t)s1 * HID + lane * 4));
        acc.x += v0.x * w0 + v1.x * w1;
        acc.y += v0.y * w0 + v1.y * w1;
        acc.z += v0.z * w0 + v1.z * w1;
        acc.w += v0.w * w0 + v1.w * w1;
    }
    if (e < end) {
        int s = __ldg(&g_col[e]);
        float w = __ldg(&g_norm_out[s]);
        float4 v = __ldg(reinterpret_cast<const float4*>(X + (size_t)s * HID + lane * 4));
        acc.x += v.x * w; acc.y += v.y * w; acc.z += v.z * w; acc.w += v.w * w;
    }
    float ni = g_norm_in[node];
    float no = g_norm_out[node];
    float4 b = *reinterpret_cast<const float4*>(bias + lane * 4);
    acc.x = fmaxf(acc.x * ni + b.x, 0.f) * no;
    acc.y = fmaxf(acc.y * ni + b.y, 0.f) * no;
    acc.z = fmaxf(acc.z * ni + b.z, 0.f) * no;
    acc.w = fmaxf(acc.w * ni + b.w, 0.f) * no;
    *reinterpret_cast<float4*>(out + (size_t)node * HID + lane * 4) = acc;
}

// ---------------- CSR SpMM (layer 2), node range [lo, hi): gather-sum, tf32-round ----
__global__ void __launch_bounds__(256)
spmm_plain(const float* __restrict__ X, float* __restrict__ out, int lo, int hi) {
    int node = lo + blockIdx.x * 4 + (threadIdx.x >> 6);
    if (node >= hi) return;
    int lane = threadIdx.x & 63;
    int beg = g_row_ptr[node], end = g_row_ptr[node + 1];
    float4 acc = make_float4(0.f, 0.f, 0.f, 0.f);
    int e = beg;
    for (; e + 2 <= end; e += 2) {
        int s0 = __ldg(&g_col[e]), s1 = __ldg(&g_col[e + 1]);
        float4 v0 = __ldg(reinterpret_cast<const float4*>(X + (size_t)s0 * HID + lane * 4));
        float4 v1 = __ldg(reinterpret_cast<const float4*>(X + (size_t)s1 * HID + lane * 4));
        acc.x += v0.x + v1.x; acc.y += v0.y + v1.y;
        acc.z += v0.z + v1.z; acc.w += v0.w + v1.w;
    }
    if (e < end) {
        int s = __ldg(&g_col[e]);
        float4 v = __ldg(reinterpret_cast<const float4*>(X + (size_t)s * HID + lane * 4));
        acc.x += v.x; acc.y += v.y; acc.z += v.z; acc.w += v.w;
    }
    acc.x = tf32_rn(acc.x); acc.y = tf32_rn(acc.y);
    acc.z = tf32_rn(acc.z); acc.w = tf32_rn(acc.w);
    *reinterpret_cast<float4*>(out + (size_t)node * HID + lane * 4) = acc;
}

// ---------------- tensor-core GEMM: cp.async 4-stage pipeline ----------------
// C[M,256] = diag(rscale?) * (A[M,K] @ B[256,K]^T) + bias  (opt relu)
template<bool RELU, bool CVTA>
__global__ void __launch_bounds__(256, 2)
gemm_cp(const float* __restrict__ A, const float* __restrict__ B,
        const float* __restrict__ bias, float* __restrict__ C,
        const float* __restrict__ rscale, int M, int K) {
    extern __shared__ float sm[];   // [4 stages A][4 stages B]
    const uint32_t smem_base = (uint32_t)__cvta_generic_to_shared(sm);

    const int tid = threadIdx.x;
    const int lane = tid & 31;
    const int wid = tid >> 5;
    const int wm = (wid & 1) * 64;
    const int wn = (wid >> 1) * 32;
    const int gid = lane >> 2;
    const int tig = lane & 3;
    const int bm = blockIdx.y * 128;
    const int bn = blockIdx.x * 128;

    const int r0 = tid >> 2, r1 = (tid + 256) >> 2;
    const int c40 = (tid & 3) * 4;
    const int ga0 = bm + r0, ga1 = bm + r1;
    const float* a_src0 = A + (size_t)(ga0 < M ? ga0 : (M - 1)) * K + c40;
    const float* a_src1 = A + (size_t)(ga1 < M ? ga1 : (M - 1)) * K + c40;
    const int asz0 = (ga0 < M) ? 16 : 0;
    const int asz1 = (ga1 < M) ? 16 : 0;
    const float* b_src0 = B + (size_t)(bn + r0) * K + c40;
    const float* b_src1 = B + (size_t)(bn + r1) * K + c40;
    const uint32_t a_off0 = (uint32_t)((r0 * 20 + c40) * 4);
    const uint32_t a_off1 = (uint32_t)((r1 * 20 + c40) * 4);

    auto issue_stage = [&](int st, int k0) {
        uint32_t abase = smem_base + (uint32_t)(st * STAGE_F * 4);
        uint32_t bbase = smem_base + (uint32_t)((GEMM_STAGES + st) * STAGE_F * 4);
        asm volatile("cp.async.cg.shared.global [%0], [%1], 16, %2;"
                     :: "r"(abase + a_off0), "l"(a_src0 + k0), "r"(asz0));
        asm volatile("cp.async.cg.shared.global [%0], [%1], 16, %2;"
                     :: "r"(abase + a_off1), "l"(a_src1 + k0), "r"(asz1));
        asm volatile("cp.async.cg.shared.global [%0], [%1], 16;"
                     :: "r"(bbase + a_off0), "l"(b_src0 + k0));
        asm volatile("cp.async.cg.shared.global [%0], [%1], 16;"
                     :: "r"(bbase + a_off1), "l"(b_src1 + k0));
        asm volatile("cp.async.commit_group;");
    };

    float acc[4][4][4];
#pragma unroll
    for (int i = 0; i < 4; i++)
#pragma unroll
        for (int j = 0; j < 4; j++)
#pragma unroll
            for (int v = 0; v < 4; v++) acc[i][j][v] = 0.f;

    const int nIt = K >> 4;

    issue_stage(0, 0);
    issue_stage(1, 16);
    issue_stage(2, 32);
    asm volatile("cp.async.wait_group 2;");
    __syncthreads();

    for (int it = 0; it < nIt; it++) {
        const int s = it % GEMM_STAGES;
        const float* As = sm + s * STAGE_F;
        const float* Bs = sm + (GEMM_STAGES + s) * STAGE_F;

#pragma unroll
        for (int kk = 0; kk < 2; kk++) {
            const int kb = kk * 8;
            float a[4][4], b[4][2];
#pragma unroll
            for (int i = 0; i < 4; i++) {
                const float* p = &As[(wm + i * 16 + gid) * 20 + kb + tig];
                a[i][0] = p[0];
                a[i][1] = p[8 * 20];
                a[i][2] = p[4];
                a[i][3] = p[8 * 20 + 4];
                if (CVTA) {
                    a[i][0] = tf32_rn(a[i][0]); a[i][1] = tf32_rn(a[i][1]);
                    a[i][2] = tf32_rn(a[i][2]); a[i][3] = tf32_rn(a[i][3]);
                }
            }
#pragma unroll
            for (int j = 0; j < 4; j++) {
                const float* p = &Bs[(wn + j * 8 + gid) * 20 + kb + tig];
                b[j][0] = p[0];
                b[j][1] = p[4];
            }
#pragma unroll
            for (int i = 0; i < 4; i++)
#pragma unroll
                for (int j = 0; j < 4; j++)
                    mma_tf32(acc[i][j], a[i], b[j]);
        }

        const int nx = it + 3;
        if (nx < nIt) issue_stage(nx % GEMM_STAGES, nx * 16);
        else asm volatile("cp.async.commit_group;");
        asm volatile("cp.async.wait_group 2;");
        __syncthreads();
    }

#pragma unroll
    for (int j = 0; j < 4; j++) {
        const int col = bn + wn + j * 8 + tig * 2;
        const float bx = bias[col], by = bias[col + 1];
#pragma unroll
        for (int i = 0; i < 4; i++) {
            const int ra = bm + wm + i * 16 + gid;
            const int rb = ra + 8;
            if (ra < M) {
                float s = rscale ? rscale[ra] : 1.f;
                float2 v;
                v.x = acc[i][j][0] * s + bx;
                v.y = acc[i][j][1] * s + by;
                if (RELU) { v.x = fmaxf(v.x, 0.f); v.y = fmaxf(v.y, 0.f); }
                *reinterpret_cast<float2*>(C + (size_t)ra * HID + col) = v;
            }
            if (rb < M) {
                float s = rscale ? rscale[rb] : 1.f;
                float2 v;
                v.x = acc[i][j][2] * s + bx;
                v.y = acc[i][j][3] * s + by;
                if (RELU) { v.x = fmaxf(v.x, 0.f); v.y = fmaxf(v.y, 0.f); }
                *reinterpret_cast<float2*>(C + (size_t)rb * HID + col) = v;
            }
        }
    }
}

// ---------------- transpose gc2_weight [K,N] -> g_WT [N,K], tf32-rounded ----------------
__global__ void transpose_kernel(const float* __restrict__ W) {
    __shared__ float t[32][33];
    int bx = blockIdx.x * 32, by = blockIdx.y * 32;
    t[threadIdx.y][threadIdx.x] = W[(size_t)(by + threadIdx.y) * HID + bx + threadIdx.x];
    __syncthreads();
    g_WT[(size_t)(bx + threadIdx.y) * HID + by + threadIdx.x] = tf32_rn(t[threadIdx.x][threadIdx.y]);
}

__global__ void tail_kernel(const float* __restrict__ sw, float* __restrict__ out, int off) {
    if (threadIdx.x < 5) out[off + threadIdx.x] = sw[threadIdx.x];
}

// ---------------- launch ----------------
extern "C" void kernel_launch(void* const* d_in, const int* in_sizes, int n_in,
                              void* d_out, int out_size) {
    const float* feat0 = (const float*)d_in[0];
    const float* feat1 = (const float*)d_in[1];
    const float* feat2 = (const float*)d_in[2];
    const float* fc_w0 = (const float*)d_in[3];
    const float* fc_b0 = (const float*)d_in[4];
    const float* fc_w1 = (const float*)d_in[5];
    const float* fc_b1 = (const float*)d_in[6];
    const float* fc_w2 = (const float*)d_in[7];
    const float* fc_b2 = (const float*)d_in[8];
    const float* gc1_bias = (const float*)d_in[9];
    const float* gc2_weight = (const float*)d_in[10];
    const float* gc2_bias = (const float*)d_in[11];
    const float* semantic_weight = (const float*)d_in[12];
    const int* src = (const int*)d_in[13];   // JAX x64-disabled -> int32
    const int* dst = (const int*)d_in[14];
    float* out = (float*)d_out;

    float *H = nullptr, *AGG = nullptr, *WT = nullptr, *NI = nullptr;
    float *W0 = nullptr, *W1 = nullptr, *W2 = nullptr;
    void *DIN = nullptr, *DOUT = nullptr;
    cudaGetSymbolAddress((void**)&H, g_H);
    cudaGetSymbolAddress((void**)&AGG, g_AGG);
    cudaGetSymbolAddress((void**)&WT, g_WT);
    cudaGetSymbolAddress((void**)&NI, g_norm_in);
    cudaGetSymbolAddress((void**)&W0, g_W0);
    cudaGetSymbolAddress((void**)&W1, g_W1);
    cudaGetSymbolAddress((void**)&W2, g_W2);
    cudaGetSymbolAddress(&DIN, g_din);
    cudaGetSymbolAddress(&DOUT, g_dout);

    static cudaStream_t sPrep = nullptr, s1 = nullptr, s2 = nullptr;
    static cudaEvent_t evFork = nullptr, evJoin = nullptr, ev1 = nullptr, ev2 = nullptr;
    static cudaEvent_t evP0 = nullptr, evG0 = nullptr;
    if (sPrep == nullptr) {
        cudaStreamCreateWithFlags(&sPrep, cudaStreamNonBlocking);
        cudaStreamCreateWithFlags(&s1, cudaStreamNonBlocking);
        cudaStreamCreateWithFlags(&s2, cudaStreamNonBlocking);
        cudaEventCreateWithFlags(&evFork, cudaEventDisableTiming);
        cudaEventCreateWithFlags(&evJoin, cudaEventDisableTiming);
        cudaEventCreateWithFlags(&ev1, cudaEventDisableTiming);
        cudaEventCreateWithFlags(&ev2, cudaEventDisableTiming);
        cudaEventCreateWithFlags(&evP0, cudaEventDisableTiming);
        cudaEventCreateWithFlags(&evG0, cudaEventDisableTiming);
        cudaFuncSetAttribute(gemm_cp<false, true>, cudaFuncAttributeMaxDynamicSharedMemorySize, GEMM_SMEM_BYTES);
        cudaFuncSetAttribute(gemm_cp<true, false>, cudaFuncAttributeMaxDynamicSharedMemorySize, GEMM_SMEM_BYTES);
    }

    cudaEventRecord(evFork, 0);
    cudaStreamWaitEvent(sPrep, evFork, 0);
    cudaStreamWaitEvent(s1, evFork, 0);
    cudaStreamWaitEvent(s2, evFork, 0);

    // ---- s1: fc1 branch ----
    cvt_weights<<<(HID * 256 / 4 + 255) / 256, 256, 0, s1>>>(fc_w1, W1, HID * 256 / 4);
    gemm_cp<false, true><<<dim3(2, (30000 + 127) / 128), 256, GEMM_SMEM_BYTES, s1>>>(
        feat1, W1, fc_b1, H + (size_t)40000 * HID, nullptr, 30000, 256);
    cudaEventRecord(ev1, s1);

    // ---- s2: fc2 branch ----
    cvt_weights<<<(HID * 128 / 4 + 255) / 256, 256, 0, s2>>>(fc_w2, W2, HID * 128 / 4);
    gemm_cp<false, true><<<dim3(2, (30000 + 127) / 128), 256, GEMM_SMEM_BYTES, s2>>>(
        feat2, W2, fc_b2, H + (size_t)70000 * HID, nullptr, 30000, 128);
    cudaEventRecord(ev2, s2);

    // ---- main: fc0 branch (concurrent with s1/s2) ----
    cvt_weights<<<(HID * 512 / 4 + 255) / 256, 256>>>(fc_w0, W0, HID * 512 / 4);
    gemm_cp<false, true><<<dim3(2, (40000 + 127) / 128), 256, GEMM_SMEM_BYTES>>>(
        feat0, W0, fc_b0, H, nullptr, 40000, 512);

    // ---- prep stream: CSR build + norms + weight transpose ----
    cudaMemsetAsync(DIN, 0, N_NODES * sizeof(int), sPrep);
    cudaMemsetAsync(DOUT, 0, N_NODES * sizeof(int), sPrep);
    hist_kernel<<<(N_EDGES + 255) / 256, 256, 0, sPrep>>>(src, dst);
    scan_a<<<N_BLK, SCAN_B, 0, sPrep>>>();
    scan_c<<<(N_NODES + 255) / 256, 256, 0, sPrep>>>();
    scatter_kernel<<<(N_EDGES + 255) / 256, 256, 0, sPrep>>>(src, dst);
    transpose_kernel<<<dim3(8, 8), dim3(32, 32), 0, sPrep>>>(gc2_weight);
    cudaEventRecord(evJoin, sPrep);

    // ---- join all branches on main ----
    cudaStreamWaitEvent(0, ev1, 0);
    cudaStreamWaitEvent(0, ev2, 0);
    cudaStreamWaitEvent(0, evJoin, 0);

    // layer 1 SpMM (full)
    spmm_scaled<<<(N_NODES + 3) / 4, 256>>>(H, AGG, gc1_bias);

    // layer 2: chunk-pipelined SpMM -> GEMM
    // chunk 0 SpMM on main, then its GEMM on s1 while main runs chunk 1 SpMM.
    spmm_plain<<<(CHUNK0 + 3) / 4, 256>>>(AGG, H, 0, CHUNK0);
    cudaEventRecord(evP0, 0);
    cudaStreamWaitEvent(s1, evP0, 0);
    gemm_cp<true, false><<<dim3(2, CHUNK0 / 128), 256, GEMM_SMEM_BYTES, s1>>>(
        H, WT, gc2_bias, out, NI, CHUNK0, 256);
    cudaEventRecord(evG0, s1);

    spmm_plain<<<(N_NODES - CHUNK0 + 3) / 4, 256>>>(AGG, H, CHUNK0, N_NODES);
    gemm_cp<true, false><<<dim3(2, (N_NODES - CHUNK0 + 127) / 128), 256, GEMM_SMEM_BYTES>>>(
        H + (size_t)CHUNK0 * HID, WT, gc2_bias, out + (size_t)CHUNK0 * HID,
        NI + CHUNK0, N_NODES - CHUNK0, 256);

    cudaStreamWaitEvent(0, evG0, 0);
    tail_kernel<<<1, 32>>>(semantic_weight, out, out_size - 5);
}

// round 15
// speedup vs baseline: 1.4521x; 1.0008x over previous
#include <cuda_runtime.h>
#include <cstdint>

#define N_NODES 100000
#define N_EDGES 300000
#define HID 256
#define SCAN_B 1024
#define N_BLK ((N_NODES + SCAN_B - 1) / SCAN_B)   // 98

// GEMM pipeline config: 4 stages
#define STAGE_F 2560
#define GEMM_STAGES 4
#define GEMM_SMEM_BYTES (GEMM_STAGES * STAGE_F * 2 * 4)   // 81920

// layer-2 chunking (3 chunks)
#define CH 33408   // multiple of 128

// ---------------- scratch ----------------
__device__ float g_H[(size_t)N_NODES * HID];
__device__ float g_AGG[(size_t)N_NODES * HID];
__device__ float g_WT[HID * HID];
__device__ float g_W0[HID * 512];
__device__ float g_W1[HID * 256];
__device__ float g_W2[HID * 128];
__device__ float g_norm_out[N_NODES];
__device__ float g_norm_in[N_NODES];
__device__ int g_din[N_NODES];
__device__ int g_dout[N_NODES];
__device__ int g_row_ptr[N_NODES + 1];
__device__ int g_cursor[N_NODES];
__device__ int g_col[N_EDGES];
__device__ int g_blksum[N_BLK];

__device__ __forceinline__ float tf32_rn(float x) {
    uint32_t r;
    asm("cvt.rna.tf32.f32 %0, %1;" : "=r"(r) : "f"(x));
    return __uint_as_float(r);
}
__device__ __forceinline__ void mma_tf32(float* c, const float* a, const float* b) {
    asm volatile(
        "mma.sync.aligned.m16n8k8.row.col.f32.tf32.tf32.f32 "
        "{%0,%1,%2,%3}, {%4,%5,%6,%7}, {%8,%9}, {%0,%1,%2,%3};"
        : "+f"(c[0]), "+f"(c[1]), "+f"(c[2]), "+f"(c[3])
        : "r"(__float_as_uint(a[0])), "r"(__float_as_uint(a[1])),
          "r"(__float_as_uint(a[2])), "r"(__float_as_uint(a[3])),
          "r"(__float_as_uint(b[0])), "r"(__float_as_uint(b[1])));
}

// ---------------- weight pre-conversion ----------------
__global__ void cvt_weights(const float* __restrict__ W, float* __restrict__ out, int n4) {
    int i = blockIdx.x * blockDim.x + threadIdx.x;
    if (i < n4) {
        float4 v = reinterpret_cast<const float4*>(W)[i];
        v.x = tf32_rn(v.x); v.y = tf32_rn(v.y); v.z = tf32_rn(v.z); v.w = tf32_rn(v.w);
        reinterpret_cast<float4*>(out)[i] = v;
    }
}

// ---------------- CSR build ----------------
__global__ void hist_kernel(const int* __restrict__ src, const int* __restrict__ dst) {
    int e = blockIdx.x * blockDim.x + threadIdx.x;
    if (e < N_EDGES) {
        atomicAdd(&g_dout[src[e]], 1);
        atomicAdd(&g_din[dst[e]], 1);
    }
}
__global__ void scan_a() {
    __shared__ int sh[SCAN_B];
    int t = threadIdx.x, idx = blockIdx.x * SCAN_B + t;
    int v = (idx < N_NODES) ? g_din[idx] : 0;
    sh[t] = v;
    __syncthreads();
#pragma unroll
    for (int off = 1; off < SCAN_B; off <<= 1) {
        int add = (t >= off) ? sh[t - off] : 0;
        __syncthreads();
        sh[t] += add;
        __syncthreads();
    }
    if (idx < N_NODES) g_row_ptr[idx + 1] = sh[t];
    if (t == SCAN_B - 1) g_blksum[blockIdx.x] = sh[t];
}
__global__ void scan_c() {
    __shared__ int red[256];
    const int t = threadIdx.x;
    const int chunk = (blockIdx.x * 256) / SCAN_B;
    int part = 0;
    for (int i = t; i < chunk; i += 256) part += g_blksum[i];
    red[t] = part;
    __syncthreads();
#pragma unroll
    for (int o = 128; o > 0; o >>= 1) {
        if (t < o) red[t] += red[t + o];
        __syncthreads();
    }
    const int base = red[0];
    int idx = blockIdx.x * 256 + t;
    if (idx == 0) g_row_ptr[0] = 0;
    if (idx < N_NODES) {
        int inc = g_row_ptr[idx + 1] + base;
        g_row_ptr[idx + 1] = inc;
        g_cursor[idx] = inc - g_din[idx];
        g_norm_in[idx]  = rsqrtf(fmaxf((float)g_din[idx], 1.f));
        g_norm_out[idx] = rsqrtf(fmaxf((float)g_dout[idx], 1.f));
    }
}
__global__ void scatter_kernel(const int* __restrict__ src, const int* __restrict__ dst) {
    int e = blockIdx.x * blockDim.x + threadIdx.x;
    if (e < N_EDGES) {
        int pos = atomicAdd(&g_cursor[dst[e]], 1);
        g_col[pos] = src[e];
    }
}

// ---------------- CSR SpMM (layer 1): masked 4-batch gather, fused epilogue ----
__global__ void __launch_bounds__(256)
spmm_scaled(const float* __restrict__ X, float* __restrict__ out, const float* __restrict__ bias) {
    int node = blockIdx.x * 4 + (threadIdx.x >> 6);
    if (node >= N_NODES) return;
    int lane = threadIdx.x & 63;
    int beg = g_row_ptr[node], end = g_row_ptr[node + 1];
    float4 acc = make_float4(0.f, 0.f, 0.f, 0.f);
    for (int base = beg; base < end; base += 4) {
        int last = end - 1;
        int e0 = base;
        int e1 = (base + 1 < end) ? base + 1 : last;
        int e2 = (base + 2 < end) ? base + 2 : last;
        int e3 = (base + 3 < end) ? base + 3 : last;
        float m1 = (base + 1 < end) ? 1.f : 0.f;
        float m2 = (base + 2 < end) ? 1.f : 0.f;
        float m3 = (base + 3 < end) ? 1.f : 0.f;
        int s0 = __ldg(&g_col[e0]), s1 = __ldg(&g_col[e1]);
        int s2 = __ldg(&g_col[e2]), s3 = __ldg(&g_col[e3]);
        float w0 = __ldg(&g_norm_out[s0]);
        float w1 = __ldg(&g_norm_out[s1]) * m1;
        float w2 = __ldg(&g_norm_out[s2]) * m2;
        float w3 = __ldg(&g_norm_out[s3]) * m3;
        float4 v0 = __ldg(reinterpret_cast<const float4*>(X + (size_t)s0 * HID + lane * 4));
        float4 v1 = __ldg(reinterpret_cast<const float4*>(X + (size_t)s1 * HID + lane * 4));
        float4 v2 = __ldg(reinterpret_cast<const float4*>(X + (size_t)s2 * HID + lane * 4));
        float4 v3 = __ldg(reinterpret_cast<const float4*>(X + (size_t)s3 * HID + lane * 4));
        acc.x += v0.x * w0 + v1.x * w1 + v2.x * w2 + v3.x * w3;
        acc.y += v0.y * w0 + v1.y * w1 + v2.y * w2 + v3.y * w3;
        acc.z += v0.z * w0 + v1.z * w1 + v2.z * w2 + v3.z * w3;
        acc.w += v0.w * w0 + v1.w * w1 + v2.w * w2 + v3.w * w3;
    }
    float ni = g_norm_in[node];
    float no = g_norm_out[node];
    float4 b = *reinterpret_cast<const float4*>(bias + lane * 4);
    acc.x = fmaxf(acc.x * ni + b.x, 0.f) * no;
    acc.y = fmaxf(acc.y * ni + b.y, 0.f) * no;
    acc.z = fmaxf(acc.z * ni + b.z, 0.f) * no;
    acc.w = fmaxf(acc.w * ni + b.w, 0.f) * no;
    *reinterpret_cast<float4*>(out + (size_t)node * HID + lane * 4) = acc;
}

// ---------------- CSR SpMM (layer 2), node range [lo, hi): masked 4-batch, tf32-round ----
__global__ void __launch_bounds__(256)
spmm_plain(const float* __restrict__ X, float* __restrict__ out, int lo, int hi) {
    int node = lo + blockIdx.x * 4 + (threadIdx.x >> 6);
    if (node >= hi) return;
    int lane = threadIdx.x & 63;
    int beg = g_row_ptr[node], end = g_row_ptr[node + 1];
    float4 acc = make_float4(0.f, 0.f, 0.f, 0.f);
    for (int base = beg; base < end; base += 4) {
        int last = end - 1;
        int e0 = base;
        int e1 = (base + 1 < end) ? base + 1 : last;
        int e2 = (base + 2 < end) ? base + 2 : last;
        int e3 = (base + 3 < end) ? base + 3 : last;
        float m1 = (base + 1 < end) ? 1.f : 0.f;
        float m2 = (base + 2 < end) ? 1.f : 0.f;
        float m3 = (base + 3 < end) ? 1.f : 0.f;
        int s0 = __ldg(&g_col[e0]), s1 = __ldg(&g_col[e1]);
        int s2 = __ldg(&g_col[e2]), s3 = __ldg(&g_col[e3]);
        float4 v0 = __ldg(reinterpret_cast<const float4*>(X + (size_t)s0 * HID + lane * 4));
        float4 v1 = __ldg(reinterpret_cast<const float4*>(X + (size_t)s1 * HID + lane * 4));
        float4 v2 = __ldg(reinterpret_cast<const float4*>(X + (size_t)s2 * HID + lane * 4));
        float4 v3 = __ldg(reinterpret_cast<const float4*>(X + (size_t)s3 * HID + lane * 4));
        acc.x += v0.x + v1.x * m1 + v2.x * m2 + v3.x * m3;
        acc.y += v0.y + v1.y * m1 + v2.y * m2 + v3.y * m3;
        acc.z += v0.z + v1.z * m1 + v2.z * m2 + v3.z * m3;
        acc.w += v0.w + v1.w * m1 + v2.w * m2 + v3.w * m3;
    }
    acc.x = tf32_rn(acc.x); acc.y = tf32_rn(acc.y);
    acc.z = tf32_rn(acc.z); acc.w = tf32_rn(acc.w);
    *reinterpret_cast<float4*>(out + (size_t)node * HID + lane * 4) = acc;
}

// ---------------- tensor-core GEMM: cp.async 4-stage pipeline ----------------
template<bool RELU, bool CVTA>
__global__ void __launch_bounds__(256, 2)
gemm_cp(const float* __restrict__ A, const float* __restrict__ B,
        const float* __restrict__ bias, float* __restrict__ C,
        const float* __restrict__ rscale, int M, int K) {
    extern __shared__ float sm[];
    const uint32_t smem_base = (uint32_t)__cvta_generic_to_shared(sm);

    const int tid = threadIdx.x;
    const int lane = tid & 31;
    const int wid = tid >> 5;
    const int wm = (wid & 1) * 64;
    const int wn = (wid >> 1) * 32;
    const int gid = lane >> 2;
    const int tig = lane & 3;
    const int bm = blockIdx.y * 128;
    const int bn = blockIdx.x * 128;

    const int r0 = tid >> 2, r1 = (tid + 256) >> 2;
    const int c40 = (tid & 3) * 4;
    const int ga0 = bm + r0, ga1 = bm + r1;
    const float* a_src0 = A + (size_t)(ga0 < M ? ga0 : (M - 1)) * K + c40;
    const float* a_src1 = A + (size_t)(ga1 < M ? ga1 : (M - 1)) * K + c40;
    const int asz0 = (ga0 < M) ? 16 : 0;
    const int asz1 = (ga1 < M) ? 16 : 0;
    const float* b_src0 = B + (size_t)(bn + r0) * K + c40;
    const float* b_src1 = B + (size_t)(bn + r1) * K + c40;
    const uint32_t a_off0 = (uint32_t)((r0 * 20 + c40) * 4);
    const uint32_t a_off1 = (uint32_t)((r1 * 20 + c40) * 4);

    auto issue_stage = [&](int st, int k0) {
        uint32_t abase = smem_base + (uint32_t)(st * STAGE_F * 4);
        uint32_t bbase = smem_base + (uint32_t)((GEMM_STAGES + st) * STAGE_F * 4);
        asm volatile("cp.async.cg.shared.global [%0], [%1], 16, %2;"
                     :: "r"(abase + a_off0), "l"(a_src0 + k0), "r"(asz0));
        asm volatile("cp.async.cg.shared.global [%0], [%1], 16, %2;"
                     :: "r"(abase + a_off1), "l"(a_src1 + k0), "r"(asz1));
        asm volatile("cp.async.cg.shared.global [%0], [%1], 16;"
                     :: "r"(bbase + a_off0), "l"(b_src0 + k0));
        asm volatile("cp.async.cg.shared.global [%0], [%1], 16;"
                     :: "r"(bbase + a_off1), "l"(b_src1 + k0));
        asm volatile("cp.async.commit_group;");
    };

    float acc[4][4][4];
#pragma unroll
    for (int i = 0; i < 4; i++)
#pragma unroll
        for (int j = 0; j < 4; j++)
#pragma unroll
            for (int v = 0; v < 4; v++) acc[i][j][v] = 0.f;

    const int nIt = K >> 4;

    issue_stage(0, 0);
    issue_stage(1, 16);
    issue_stage(2, 32);
    asm volatile("cp.async.wait_group 2;");
    __syncthreads();

    for (int it = 0; it < nIt; it++) {
        const int s = it % GEMM_STAGES;
        const float* As = sm + s * STAGE_F;
        const float* Bs = sm + (GEMM_STAGES + s) * STAGE_F;

#pragma unroll
        for (int kk = 0; kk < 2; kk++) {
            const int kb = kk * 8;
            float a[4][4], b[4][2];
#pragma unroll
            for (int i = 0; i < 4; i++) {
                const float* p = &As[(wm + i * 16 + gid) * 20 + kb + tig];
                a[i][0] = p[0];
                a[i][1] = p[8 * 20];
                a[i][2] = p[4];
                a[i][3] = p[8 * 20 + 4];
                if (CVTA) {
                    a[i][0] = tf32_rn(a[i][0]); a[i][1] = tf32_rn(a[i][1]);
                    a[i][2] = tf32_rn(a[i][2]); a[i][3] = tf32_rn(a[i][3]);
                }
            }
#pragma unroll
            for (int j = 0; j < 4; j++) {
                const float* p = &Bs[(wn + j * 8 + gid) * 20 + kb + tig];
                b[j][0] = p[0];
                b[j][1] = p[4];
            }
#pragma unroll
            for (int i = 0; i < 4; i++)
#pragma unroll
                for (int j = 0; j < 4; j++)
                    mma_tf32(acc[i][j], a[i], b[j]);
        }

        const int nx = it + 3;
        if (nx < nIt) issue_stage(nx % GEMM_STAGES, nx * 16);
        else asm volatile("cp.async.commit_group;");
        asm volatile("cp.async.wait_group 2;");
        __syncthreads();
    }

#pragma unroll
    for (int j = 0; j < 4; j++) {
        const int col = bn + wn + j * 8 + tig * 2;
        const float bx = bias[col], by = bias[col + 1];
#pragma unroll
        for (int i = 0; i < 4; i++) {
            const int ra = bm + wm + i * 16 + gid;
            const int rb = ra + 8;
            if (ra < M) {
                float s = rscale ? rscale[ra] : 1.f;
                float2 v;
                v.x = acc[i][j][0] * s + bx;
                v.y = acc[i][j][1] * s + by;
                if (RELU) { v.x = fmaxf(v.x, 0.f); v.y = fmaxf(v.y, 0.f); }
                *reinterpret_cast<float2*>(C + (size_t)ra * HID + col) = v;
            }
            if (rb < M) {
                float s = rscale ? rscale[rb] : 1.f;
                float2 v;
                v.x = acc[i][j][2] * s + bx;
                v.y = acc[i][j][3] * s + by;
                if (RELU) { v.x = fmaxf(v.x, 0.f); v.y = fmaxf(v.y, 0.f); }
                *reinterpret_cast<float2*>(C + (size_t)rb * HID + col) = v;
            }
        }
    }
}

// ---------------- transpose gc2_weight [K,N] -> g_WT [N,K], tf32-rounded ----------------
__global__ void transpose_kernel(const float* __restrict__ W) {
    __shared__ float t[32][33];
    int bx = blockIdx.x * 32, by = blockIdx.y * 32;
    t[threadIdx.y][threadIdx.x] = W[(size_t)(by + threadIdx.y) * HID + bx + threadIdx.x];
    __syncthreads();
    g_WT[(size_t)(bx + threadIdx.y) * HID + by + threadIdx.x] = tf32_rn(t[threadIdx.x][threadIdx.y]);
}

__global__ void tail_kernel(const float* __restrict__ sw, float* __restrict__ out, int off) {
    if (threadIdx.x < 5) out[off + threadIdx.x] = sw[threadIdx.x];
}

// ---------------- launch ----------------
extern "C" void kernel_launch(void* const* d_in, const int* in_sizes, int n_in,
                              void* d_out, int out_size) {
    const float* feat0 = (const float*)d_in[0];
    const float* feat1 = (const float*)d_in[1];
    const float* feat2 = (const float*)d_in[2];
    const float* fc_w0 = (const float*)d_in[3];
    const float* fc_b0 = (const float*)d_in[4];
    const float* fc_w1 = (const float*)d_in[5];
    const float* fc_b1 = (const float*)d_in[6];
    const float* fc_w2 = (const float*)d_in[7];
    const float* fc_b2 = (const float*)d_in[8];
    const float* gc1_bias = (const float*)d_in[9];
    const float* gc2_weight = (const float*)d_in[10];
    const float* gc2_bias = (const float*)d_in[11];
    const float* semantic_weight = (const float*)d_in[12];
    const int* src = (const int*)d_in[13];   // JAX x64-disabled -> int32
    const int* dst = (const int*)d_in[14];
    float* out = (float*)d_out;

    float *H = nullptr, *AGG = nullptr, *WT = nullptr, *NI = nullptr;
    float *W0 = nullptr, *W1 = nullptr, *W2 = nullptr;
    void *DIN = nullptr, *DOUT = nullptr;
    cudaGetSymbolAddress((void**)&H, g_H);
    cudaGetSymbolAddress((void**)&AGG, g_AGG);
    cudaGetSymbolAddress((void**)&WT, g_WT);
    cudaGetSymbolAddress((void**)&NI, g_norm_in);
    cudaGetSymbolAddress((void**)&W0, g_W0);
    cudaGetSymbolAddress((void**)&W1, g_W1);
    cudaGetSymbolAddress((void**)&W2, g_W2);
    cudaGetSymbolAddress(&DIN, g_din);
    cudaGetSymbolAddress(&DOUT, g_dout);

    static cudaStream_t sPrep = nullptr, s1 = nullptr, s2 = nullptr;
    static cudaEvent_t evFork = nullptr, evJoin = nullptr, ev1 = nullptr, ev2 = nullptr;
    static cudaEvent_t evP0 = nullptr, evP1 = nullptr, evG = nullptr;
    if (sPrep == nullptr) {
        cudaStreamCreateWithFlags(&sPrep, cudaStreamNonBlocking);
        cudaStreamCreateWithFlags(&s1, cudaStreamNonBlocking);
        cudaStreamCreateWithFlags(&s2, cudaStreamNonBlocking);
        cudaEventCreateWithFlags(&evFork, cudaEventDisableTiming);
        cudaEventCreateWithFlags(&evJoin, cudaEventDisableTiming);
        cudaEventCreateWithFlags(&ev1, cudaEventDisableTiming);
        cudaEventCreateWithFlags(&ev2, cudaEventDisableTiming);
        cudaEventCreateWithFlags(&evP0, cudaEventDisableTiming);
        cudaEventCreateWithFlags(&evP1, cudaEventDisableTiming);
        cudaEventCreateWithFlags(&evG, cudaEventDisableTiming);
        cudaFuncSetAttribute(gemm_cp<false, true>, cudaFuncAttributeMaxDynamicSharedMemorySize, GEMM_SMEM_BYTES);
        cudaFuncSetAttribute(gemm_cp<true, false>, cudaFuncAttributeMaxDynamicSharedMemorySize, GEMM_SMEM_BYTES);
    }

    cudaEventRecord(evFork, 0);
    cudaStreamWaitEvent(sPrep, evFork, 0);
    cudaStreamWaitEvent(s1, evFork, 0);
    cudaStreamWaitEvent(s2, evFork, 0);

    // ---- s1: fc1 branch ----
    cvt_weights<<<(HID * 256 / 4 + 255) / 256, 256, 0, s1>>>(fc_w1, W1, HID * 256 / 4);
    gemm_cp<false, true><<<dim3(2, (30000 + 127) / 128), 256, GEMM_SMEM_BYTES, s1>>>(
        feat1, W1, fc_b1, H + (size_t)40000 * HID, nullptr, 30000, 256);
    cudaEventRecord(ev1, s1);

    // ---- s2: fc2 branch ----
    cvt_weights<<<(HID * 128 / 4 + 255) / 256, 256, 0, s2>>>(fc_w2, W2, HID * 128 / 4);
    gemm_cp<false, true><<<dim3(2, (30000 + 127) / 128), 256, GEMM_SMEM_BYTES, s2>>>(
        feat2, W2, fc_b2, H + (size_t)70000 * HID, nullptr, 30000, 128);
    cudaEventRecord(ev2, s2);

    // ---- main: fc0 branch (concurrent with s1/s2) ----
    cvt_weights<<<(HID * 512 / 4 + 255) / 256, 256>>>(fc_w0, W0, HID * 512 / 4);
    gemm_cp<false, true><<<dim3(2, (40000 + 127) / 128), 256, GEMM_SMEM_BYTES>>>(
        feat0, W0, fc_b0, H, nullptr, 40000, 512);

    // ---- prep stream: CSR build + norms + weight transpose ----
    cudaMemsetAsync(DIN, 0, N_NODES * sizeof(int), sPrep);
    cudaMemsetAsync(DOUT, 0, N_NODES * sizeof(int), sPrep);
    hist_kernel<<<(N_EDGES + 255) / 256, 256, 0, sPrep>>>(src, dst);
    scan_a<<<N_BLK, SCAN_B, 0, sPrep>>>();
    scan_c<<<(N_NODES + 255) / 256, 256, 0, sPrep>>>();
    scatter_kernel<<<(N_EDGES + 255) / 256, 256, 0, sPrep>>>(src, dst);
    transpose_kernel<<<dim3(8, 8), dim3(32, 32), 0, sPrep>>>(gc2_weight);
    cudaEventRecord(evJoin, sPrep);

    // ---- join all branches on main ----
    cudaStreamWaitEvent(0, ev1, 0);
    cudaStreamWaitEvent(0, ev2, 0);
    cudaStreamWaitEvent(0, evJoin, 0);

    // layer 1 SpMM (full)
    spmm_scaled<<<(N_NODES + 3) / 4, 256>>>(H, AGG, gc1_bias);

    // layer 2: 3-chunk pipelined SpMM (main) -> GEMM (s1)
    spmm_plain<<<(CH + 3) / 4, 256>>>(AGG, H, 0, CH);
    cudaEventRecord(evP0, 0);
    cudaStreamWaitEvent(s1, evP0, 0);
    gemm_cp<true, false><<<dim3(2, CH / 128), 256, GEMM_SMEM_BYTES, s1>>>(
        H, WT, gc2_bias, out, NI, CH, 256);

    spmm_plain<<<(CH + 3) / 4, 256>>>(AGG, H, CH, 2 * CH);
    cudaEventRecord(evP1, 0);
    cudaStreamWaitEvent(s1, evP1, 0);
    gemm_cp<true, false><<<dim3(2, CH / 128), 256, GEMM_SMEM_BYTES, s1>>>(
        H + (size_t)CH * HID, WT, gc2_bias, out + (size_t)CH * HID, NI + CH, CH, 256);
    cudaEventRecord(evG, s1);

    spmm_plain<<<(N_NODES - 2 * CH + 3) / 4, 256>>>(AGG, H, 2 * CH, N_NODES);
    gemm_cp<true, false><<<dim3(2, (N_NODES - 2 * CH + 127) / 128), 256, GEMM_SMEM_BYTES>>>(
        H + (size_t)(2 * CH) * HID, WT, gc2_bias, out + (size_t)(2 * CH) * HID,
        NI + 2 * CH, N_NODES - 2 * CH, 256);

    cudaStreamWaitEvent(0, evG, 0);
    tail_kernel<<<1, 32>>>(semantic_weight, out, out_size - 5);
}

// round 16
// speedup vs baseline: 1.5774x; 1.0863x over previous
#include <cuda_runtime.h>
#include <cuda_fp16.h>
#include <cstdint>

#define N_NODES 100000
#define N_EDGES 300000
#define HID 256
#define SCAN_B 1024
#define N_BLK ((N_NODES + SCAN_B - 1) / SCAN_B)   // 98

// GEMM pipeline config: 4 stages
#define STAGE_F 2560
#define GEMM_STAGES 4
#define GEMM_SMEM_BYTES (GEMM_STAGES * STAGE_F * 2 * 4)   // 81920

// layer-2 chunking (3 chunks)
#define CH 33408   // multiple of 128

// ---------------- scratch ----------------
__device__ __half g_Hh[(size_t)N_NODES * HID];    // fc outputs (fp16)
__device__ __half g_AGGh[(size_t)N_NODES * HID];  // layer-1 output (fp16)
__device__ float g_H[(size_t)N_NODES * HID];      // layer-2 agg (fp32, tf32-rounded)
__device__ float g_WT[HID * HID];
__device__ float g_W0[HID * 512];
__device__ float g_W1[HID * 256];
__device__ float g_W2[HID * 128];
__device__ float g_norm_out[N_NODES];
__device__ float g_norm_in[N_NODES];
__device__ int g_din[N_NODES];
__device__ int g_dout[N_NODES];
__device__ int g_row_ptr[N_NODES + 1];
__device__ int g_cursor[N_NODES];
__device__ int g_col[N_EDGES];
__device__ int g_blksum[N_BLK];

__device__ __forceinline__ float tf32_rn(float x) {
    uint32_t r;
    asm("cvt.rna.tf32.f32 %0, %1;" : "=r"(r) : "f"(x));
    return __uint_as_float(r);
}
__device__ __forceinline__ void mma_tf32(float* c, const float* a, const float* b) {
    asm volatile(
        "mma.sync.aligned.m16n8k8.row.col.f32.tf32.tf32.f32 "
        "{%0,%1,%2,%3}, {%4,%5,%6,%7}, {%8,%9}, {%0,%1,%2,%3};"
        : "+f"(c[0]), "+f"(c[1]), "+f"(c[2]), "+f"(c[3])
        : "r"(__float_as_uint(a[0])), "r"(__float_as_uint(a[1])),
          "r"(__float_as_uint(a[2])), "r"(__float_as_uint(a[3])),
          "r"(__float_as_uint(b[0])), "r"(__float_as_uint(b[1])));
}
// 4 halves -> float4
__device__ __forceinline__ float4 ldh4(const __half* p) {
    uint2 r = __ldg(reinterpret_cast<const uint2*>(p));
    __half2 a = *reinterpret_cast<__half2*>(&r.x);
    __half2 b = *reinterpret_cast<__half2*>(&r.y);
    float2 fa = __half22float2(a), fb = __half22float2(b);
    return make_float4(fa.x, fa.y, fb.x, fb.y);
}
__device__ __forceinline__ void sth4(__half* p, float4 v) {
    __half2 a = __floats2half2_rn(v.x, v.y);
    __half2 b = __floats2half2_rn(v.z, v.w);
    uint2 r;
    r.x = *reinterpret_cast<uint32_t*>(&a);
    r.y = *reinterpret_cast<uint32_t*>(&b);
    *reinterpret_cast<uint2*>(p) = r;
}

// ---------------- weight pre-conversion ----------------
__global__ void cvt_weights(const float* __restrict__ W, float* __restrict__ out, int n4) {
    int i = blockIdx.x * blockDim.x + threadIdx.x;
    if (i < n4) {
        float4 v = reinterpret_cast<const float4*>(W)[i];
        v.x = tf32_rn(v.x); v.y = tf32_rn(v.y); v.z = tf32_rn(v.z); v.w = tf32_rn(v.w);
        reinterpret_cast<float4*>(out)[i] = v;
    }
}

// ---------------- CSR build ----------------
__global__ void hist_kernel(const int* __restrict__ src, const int* __restrict__ dst) {
    int e = blockIdx.x * blockDim.x + threadIdx.x;
    if (e < N_EDGES) {
        atomicAdd(&g_dout[src[e]], 1);
        atomicAdd(&g_din[dst[e]], 1);
    }
}
__global__ void scan_a() {
    __shared__ int sh[SCAN_B];
    int t = threadIdx.x, idx = blockIdx.x * SCAN_B + t;
    int v = (idx < N_NODES) ? g_din[idx] : 0;
    sh[t] = v;
    __syncthreads();
#pragma unroll
    for (int off = 1; off < SCAN_B; off <<= 1) {
        int add = (t >= off) ? sh[t - off] : 0;
        __syncthreads();
        sh[t] += add;
        __syncthreads();
    }
    if (idx < N_NODES) g_row_ptr[idx + 1] = sh[t];
    if (t == SCAN_B - 1) g_blksum[blockIdx.x] = sh[t];
}
__global__ void scan_c() {
    __shared__ int red[256];
    const int t = threadIdx.x;
    const int chunk = (blockIdx.x * 256) / SCAN_B;
    int part = 0;
    for (int i = t; i < chunk; i += 256) part += g_blksum[i];
    red[t] = part;
    __syncthreads();
#pragma unroll
    for (int o = 128; o > 0; o >>= 1) {
        if (t < o) red[t] += red[t + o];
        __syncthreads();
    }
    const int base = red[0];
    int idx = blockIdx.x * 256 + t;
    if (idx == 0) g_row_ptr[0] = 0;
    if (idx < N_NODES) {
        int inc = g_row_ptr[idx + 1] + base;
        g_row_ptr[idx + 1] = inc;
        g_cursor[idx] = inc - g_din[idx];
        g_norm_in[idx]  = rsqrtf(fmaxf((float)g_din[idx], 1.f));
        g_norm_out[idx] = rsqrtf(fmaxf((float)g_dout[idx], 1.f));
    }
}
__global__ void scatter_kernel(const int* __restrict__ src, const int* __restrict__ dst) {
    int e = blockIdx.x * blockDim.x + threadIdx.x;
    if (e < N_EDGES) {
        int pos = atomicAdd(&g_cursor[dst[e]], 1);
        g_col[pos] = src[e];
    }
}

// ---------------- CSR SpMM (layer 1): fp16 gathers, fp32 accum, fp16 out ----------------
__global__ void __launch_bounds__(256)
spmm_scaled(const __half* __restrict__ X, __half* __restrict__ out,
            const float* __restrict__ bias) {
    int node = blockIdx.x * 4 + (threadIdx.x >> 6);
    if (node >= N_NODES) return;
    int lane = threadIdx.x & 63;
    int beg = g_row_ptr[node], end = g_row_ptr[node + 1];
    float4 acc = make_float4(0.f, 0.f, 0.f, 0.f);
    for (int base = beg; base < end; base += 4) {
        int last = end - 1;
        int e0 = base;
        int e1 = (base + 1 < end) ? base + 1 : last;
        int e2 = (base + 2 < end) ? base + 2 : last;
        int e3 = (base + 3 < end) ? base + 3 : last;
        float m1 = (base + 1 < end) ? 1.f : 0.f;
        float m2 = (base + 2 < end) ? 1.f : 0.f;
        float m3 = (base + 3 < end) ? 1.f : 0.f;
        int s0 = __ldg(&g_col[e0]), s1 = __ldg(&g_col[e1]);
        int s2 = __ldg(&g_col[e2]), s3 = __ldg(&g_col[e3]);
        float w0 = __ldg(&g_norm_out[s0]);
        float w1 = __ldg(&g_norm_out[s1]) * m1;
        float w2 = __ldg(&g_norm_out[s2]) * m2;
        float w3 = __ldg(&g_norm_out[s3]) * m3;
        float4 v0 = ldh4(X + (size_t)s0 * HID + lane * 4);
        float4 v1 = ldh4(X + (size_t)s1 * HID + lane * 4);
        float4 v2 = ldh4(X + (size_t)s2 * HID + lane * 4);
        float4 v3 = ldh4(X + (size_t)s3 * HID + lane * 4);
        acc.x += v0.x * w0 + v1.x * w1 + v2.x * w2 + v3.x * w3;
        acc.y += v0.y * w0 + v1.y * w1 + v2.y * w2 + v3.y * w3;
        acc.z += v0.z * w0 + v1.z * w1 + v2.z * w2 + v3.z * w3;
        acc.w += v0.w * w0 + v1.w * w1 + v2.w * w2 + v3.w * w3;
    }
    float ni = g_norm_in[node];
    float no = g_norm_out[node];
    float4 b = *reinterpret_cast<const float4*>(bias + lane * 4);
    acc.x = fmaxf(acc.x * ni + b.x, 0.f) * no;
    acc.y = fmaxf(acc.y * ni + b.y, 0.f) * no;
    acc.z = fmaxf(acc.z * ni + b.z, 0.f) * no;
    acc.w = fmaxf(acc.w * ni + b.w, 0.f) * no;
    sth4(out + (size_t)node * HID + lane * 4, acc);
}

// ---------------- CSR SpMM (layer 2): fp16 gathers, fp32 accum, tf32-rounded fp32 out ----
__global__ void __launch_bounds__(256)
spmm_plain(const __half* __restrict__ X, float* __restrict__ out, int lo, int hi) {
    int node = lo + blockIdx.x * 4 + (threadIdx.x >> 6);
    if (node >= hi) return;
    int lane = threadIdx.x & 63;
    int beg = g_row_ptr[node], end = g_row_ptr[node + 1];
    float4 acc = make_float4(0.f, 0.f, 0.f, 0.f);
    for (int base = beg; base < end; base += 4) {
        int last = end - 1;
        int e0 = base;
        int e1 = (base + 1 < end) ? base + 1 : last;
        int e2 = (base + 2 < end) ? base + 2 : last;
        int e3 = (base + 3 < end) ? base + 3 : last;
        float m1 = (base + 1 < end) ? 1.f : 0.f;
        float m2 = (base + 2 < end) ? 1.f : 0.f;
        float m3 = (base + 3 < end) ? 1.f : 0.f;
        int s0 = __ldg(&g_col[e0]), s1 = __ldg(&g_col[e1]);
        int s2 = __ldg(&g_col[e2]), s3 = __ldg(&g_col[e3]);
        float4 v0 = ldh4(X + (size_t)s0 * HID + lane * 4);
        float4 v1 = ldh4(X + (size_t)s1 * HID + lane * 4);
        float4 v2 = ldh4(X + (size_t)s2 * HID + lane * 4);
        float4 v3 = ldh4(X + (size_t)s3 * HID + lane * 4);
        acc.x += v0.x + v1.x * m1 + v2.x * m2 + v3.x * m3;
        acc.y += v0.y + v1.y * m1 + v2.y * m2 + v3.y * m3;
        acc.z += v0.z + v1.z * m1 + v2.z * m2 + v3.z * m3;
        acc.w += v0.w + v1.w * m1 + v2.w * m2 + v3.w * m3;
    }
    acc.x = tf32_rn(acc.x); acc.y = tf32_rn(acc.y);
    acc.z = tf32_rn(acc.z); acc.w = tf32_rn(acc.w);
    *reinterpret_cast<float4*>(out + (size_t)node * HID + lane * 4) = acc;
}

// ---------------- tensor-core GEMM: cp.async 4-stage pipeline ----------------
// HOUT: write fp16 output (fc layers). Otherwise fp32.
template<bool RELU, bool CVTA, bool HOUT>
__global__ void __launch_bounds__(256, 2)
gemm_cp(const float* __restrict__ A, const float* __restrict__ B,
        const float* __restrict__ bias, float* __restrict__ C,
        const float* __restrict__ rscale, int M, int K) {
    extern __shared__ float sm[];
    const uint32_t smem_base = (uint32_t)__cvta_generic_to_shared(sm);

    const int tid = threadIdx.x;
    const int lane = tid & 31;
    const int wid = tid >> 5;
    const int wm = (wid & 1) * 64;
    const int wn = (wid >> 1) * 32;
    const int gid = lane >> 2;
    const int tig = lane & 3;
    const int bm = blockIdx.y * 128;
    const int bn = blockIdx.x * 128;

    const int r0 = tid >> 2, r1 = (tid + 256) >> 2;
    const int c40 = (tid & 3) * 4;
    const int ga0 = bm + r0, ga1 = bm + r1;
    const float* a_src0 = A + (size_t)(ga0 < M ? ga0 : (M - 1)) * K + c40;
    const float* a_src1 = A + (size_t)(ga1 < M ? ga1 : (M - 1)) * K + c40;
    const int asz0 = (ga0 < M) ? 16 : 0;
    const int asz1 = (ga1 < M) ? 16 : 0;
    const float* b_src0 = B + (size_t)(bn + r0) * K + c40;
    const float* b_src1 = B + (size_t)(bn + r1) * K + c40;
    const uint32_t a_off0 = (uint32_t)((r0 * 20 + c40) * 4);
    const uint32_t a_off1 = (uint32_t)((r1 * 20 + c40) * 4);

    auto issue_stage = [&](int st, int k0) {
        uint32_t abase = smem_base + (uint32_t)(st * STAGE_F * 4);
        uint32_t bbase = smem_base + (uint32_t)((GEMM_STAGES + st) * STAGE_F * 4);
        asm volatile("cp.async.cg.shared.global [%0], [%1], 16, %2;"
                     :: "r"(abase + a_off0), "l"(a_src0 + k0), "r"(asz0));
        asm volatile("cp.async.cg.shared.global [%0], [%1], 16, %2;"
                     :: "r"(abase + a_off1), "l"(a_src1 + k0), "r"(asz1));
        asm volatile("cp.async.cg.shared.global [%0], [%1], 16;"
                     :: "r"(bbase + a_off0), "l"(b_src0 + k0));
        asm volatile("cp.async.cg.shared.global [%0], [%1], 16;"
                     :: "r"(bbase + a_off1), "l"(b_src1 + k0));
        asm volatile("cp.async.commit_group;");
    };

    float acc[4][4][4];
#pragma unroll
    for (int i = 0; i < 4; i++)
#pragma unroll
        for (int j = 0; j < 4; j++)
#pragma unroll
            for (int v = 0; v < 4; v++) acc[i][j][v] = 0.f;

    const int nIt = K >> 4;

    issue_stage(0, 0);
    issue_stage(1, 16);
    issue_stage(2, 32);
    asm volatile("cp.async.wait_group 2;");
    __syncthreads();

    for (int it = 0; it < nIt; it++) {
        const int s = it % GEMM_STAGES;
        const float* As = sm + s * STAGE_F;
        const float* Bs = sm + (GEMM_STAGES + s) * STAGE_F;

#pragma unroll
        for (int kk = 0; kk < 2; kk++) {
            const int kb = kk * 8;
            float a[4][4], b[4][2];
#pragma unroll
            for (int i = 0; i < 4; i++) {
                const float* p = &As[(wm + i * 16 + gid) * 20 + kb + tig];
                a[i][0] = p[0];
                a[i][1] = p[8 * 20];
                a[i][2] = p[4];
                a[i][3] = p[8 * 20 + 4];
                if (CVTA) {
                    a[i][0] = tf32_rn(a[i][0]); a[i][1] = tf32_rn(a[i][1]);
                    a[i][2] = tf32_rn(a[i][2]); a[i][3] = tf32_rn(a[i][3]);
                }
            }
#pragma unroll
            for (int j = 0; j < 4; j++) {
                const float* p = &Bs[(wn + j * 8 + gid) * 20 + kb + tig];
                b[j][0] = p[0];
                b[j][1] = p[4];
            }
#pragma unroll
            for (int i = 0; i < 4; i++)
#pragma unroll
                for (int j = 0; j < 4; j++)
                    mma_tf32(acc[i][j], a[i], b[j]);
        }

        const int nx = it + 3;
        if (nx < nIt) issue_stage(nx % GEMM_STAGES, nx * 16);
        else asm volatile("cp.async.commit_group;");
        asm volatile("cp.async.wait_group 2;");
        __syncthreads();
    }

#pragma unroll
    for (int j = 0; j < 4; j++) {
        const int col = bn + wn + j * 8 + tig * 2;
        const float bx = bias[col], by = bias[col + 1];
#pragma unroll
        for (int i = 0; i < 4; i++) {
            const int ra = bm + wm + i * 16 + gid;
            const int rb = ra + 8;
            if (ra < M) {
                float s = rscale ? rscale[ra] : 1.f;
                float2 v;
                v.x = acc[i][j][0] * s + bx;
                v.y = acc[i][j][1] * s + by;
                if (RELU) { v.x = fmaxf(v.x, 0.f); v.y = fmaxf(v.y, 0.f); }
                if (HOUT) {
                    __half2 h = __floats2half2_rn(v.x, v.y);
                    *reinterpret_cast<__half2*>(reinterpret_cast<__half*>(C) + (size_t)ra * HID + col) = h;
                } else {
                    *reinterpret_cast<float2*>(C + (size_t)ra * HID + col) = v;
                }
            }
            if (rb < M) {
                float s = rscale ? rscale[rb] : 1.f;
                float2 v;
                v.x = acc[i][j][2] * s + bx;
                v.y = acc[i][j][3] * s + by;
                if (RELU) { v.x = fmaxf(v.x, 0.f); v.y = fmaxf(v.y, 0.f); }
                if (HOUT) {
                    __half2 h = __floats2half2_rn(v.x, v.y);
                    *reinterpret_cast<__half2*>(reinterpret_cast<__half*>(C) + (size_t)rb * HID + col) = h;
                } else {
                    *reinterpret_cast<float2*>(C + (size_t)rb * HID + col) = v;
                }
            }
        }
    }
}

// ---------------- transpose gc2_weight [K,N] -> g_WT [N,K], tf32-rounded ----------------
__global__ void transpose_kernel(const float* __restrict__ W) {
    __shared__ float t[32][33];
    int bx = blockIdx.x * 32, by = blockIdx.y * 32;
    t[threadIdx.y][threadIdx.x] = W[(size_t)(by + threadIdx.y) * HID + bx + threadIdx.x];
    __syncthreads();
    g_WT[(size_t)(bx + threadIdx.y) * HID + by + threadIdx.x] = tf32_rn(t[threadIdx.x][threadIdx.y]);
}

__global__ void tail_kernel(const float* __restrict__ sw, float* __restrict__ out, int off) {
    if (threadIdx.x < 5) out[off + threadIdx.x] = sw[threadIdx.x];
}

// ---------------- launch ----------------
extern "C" void kernel_launch(void* const* d_in, const int* in_sizes, int n_in,
                              void* d_out, int out_size) {
    const float* feat0 = (const float*)d_in[0];
    const float* feat1 = (const float*)d_in[1];
    const float* feat2 = (const float*)d_in[2];
    const float* fc_w0 = (const float*)d_in[3];
    const float* fc_b0 = (const float*)d_in[4];
    const float* fc_w1 = (const float*)d_in[5];
    const float* fc_b1 = (const float*)d_in[6];
    const float* fc_w2 = (const float*)d_in[7];
    const float* fc_b2 = (const float*)d_in[8];
    const float* gc1_bias = (const float*)d_in[9];
    const float* gc2_weight = (const float*)d_in[10];
    const float* gc2_bias = (const float*)d_in[11];
    const float* semantic_weight = (const float*)d_in[12];
    const int* src = (const int*)d_in[13];   // JAX x64-disabled -> int32
    const int* dst = (const int*)d_in[14];
    float* out = (float*)d_out;

    float *H = nullptr, *WT = nullptr, *NI = nullptr;
    float *W0 = nullptr, *W1 = nullptr, *W2 = nullptr;
    __half *Hh = nullptr, *AGGh = nullptr;
    void *DIN = nullptr, *DOUT = nullptr;
    cudaGetSymbolAddress((void**)&H, g_H);
    cudaGetSymbolAddress((void**)&Hh, g_Hh);
    cudaGetSymbolAddress((void**)&AGGh, g_AGGh);
    cudaGetSymbolAddress((void**)&WT, g_WT);
    cudaGetSymbolAddress((void**)&NI, g_norm_in);
    cudaGetSymbolAddress((void**)&W0, g_W0);
    cudaGetSymbolAddress((void**)&W1, g_W1);
    cudaGetSymbolAddress((void**)&W2, g_W2);
    cudaGetSymbolAddress(&DIN, g_din);
    cudaGetSymbolAddress(&DOUT, g_dout);

    static cudaStream_t sPrep = nullptr, s1 = nullptr, s2 = nullptr;
    static cudaEvent_t evFork = nullptr, evJoin = nullptr, ev1 = nullptr, ev2 = nullptr;
    static cudaEvent_t evP0 = nullptr, evP1 = nullptr, evG = nullptr;
    if (sPrep == nullptr) {
        cudaStreamCreateWithFlags(&sPrep, cudaStreamNonBlocking);
        cudaStreamCreateWithFlags(&s1, cudaStreamNonBlocking);
        cudaStreamCreateWithFlags(&s2, cudaStreamNonBlocking);
        cudaEventCreateWithFlags(&evFork, cudaEventDisableTiming);
        cudaEventCreateWithFlags(&evJoin, cudaEventDisableTiming);
        cudaEventCreateWithFlags(&ev1, cudaEventDisableTiming);
        cudaEventCreateWithFlags(&ev2, cudaEventDisableTiming);
        cudaEventCreateWithFlags(&evP0, cudaEventDisableTiming);
        cudaEventCreateWithFlags(&evP1, cudaEventDisableTiming);
        cudaEventCreateWithFlags(&evG, cudaEventDisableTiming);
        cudaFuncSetAttribute(gemm_cp<false, true, true>, cudaFuncAttributeMaxDynamicSharedMemorySize, GEMM_SMEM_BYTES);
        cudaFuncSetAttribute(gemm_cp<true, false, false>, cudaFuncAttributeMaxDynamicSharedMemorySize, GEMM_SMEM_BYTES);
    }

    cudaEventRecord(evFork, 0);
    cudaStreamWaitEvent(sPrep, evFork, 0);
    cudaStreamWaitEvent(s1, evFork, 0);
    cudaStreamWaitEvent(s2, evFork, 0);

    // ---- s1: fc1 branch (fp16 output) ----
    cvt_weights<<<(HID * 256 / 4 + 255) / 256, 256, 0, s1>>>(fc_w1, W1, HID * 256 / 4);
    gemm_cp<false, true, true><<<dim3(2, (30000 + 127) / 128), 256, GEMM_SMEM_BYTES, s1>>>(
        feat1, W1, fc_b1, (float*)(Hh + (size_t)40000 * HID), nullptr, 30000, 256);
    cudaEventRecord(ev1, s1);

    // ---- s2: fc2 branch ----
    cvt_weights<<<(HID * 128 / 4 + 255) / 256, 256, 0, s2>>>(fc_w2, W2, HID * 128 / 4);
    gemm_cp<false, true, true><<<dim3(2, (30000 + 127) / 128), 256, GEMM_SMEM_BYTES, s2>>>(
        feat2, W2, fc_b2, (float*)(Hh + (size_t)70000 * HID), nullptr, 30000, 128);
    cudaEventRecord(ev2, s2);

    // ---- main: fc0 branch ----
    cvt_weights<<<(HID * 512 / 4 + 255) / 256, 256>>>(fc_w0, W0, HID * 512 / 4);
    gemm_cp<false, true, true><<<dim3(2, (40000 + 127) / 128), 256, GEMM_SMEM_BYTES>>>(
        feat0, W0, fc_b0, (float*)Hh, nullptr, 40000, 512);

    // ---- prep stream: CSR build + norms + weight transpose ----
    cudaMemsetAsync(DIN, 0, N_NODES * sizeof(int), sPrep);
    cudaMemsetAsync(DOUT, 0, N_NODES * sizeof(int), sPrep);
    hist_kernel<<<(N_EDGES + 255) / 256, 256, 0, sPrep>>>(src, dst);
    scan_a<<<N_BLK, SCAN_B, 0, sPrep>>>();
    scan_c<<<(N_NODES + 255) / 256, 256, 0, sPrep>>>();
    scatter_kernel<<<(N_EDGES + 255) / 256, 256, 0, sPrep>>>(src, dst);
    transpose_kernel<<<dim3(8, 8), dim3(32, 32), 0, sPrep>>>(gc2_weight);
    cudaEventRecord(evJoin, sPrep);

    // ---- join all branches on main ----
    cudaStreamWaitEvent(0, ev1, 0);
    cudaStreamWaitEvent(0, ev2, 0);
    cudaStreamWaitEvent(0, evJoin, 0);

    // layer 1 SpMM (full, fp16 in/out)
    spmm_scaled<<<(N_NODES + 3) / 4, 256>>>(Hh, AGGh, gc1_bias);

    // layer 2: 3-chunk pipelined SpMM (main) -> GEMM (s1)
    spmm_plain<<<(CH + 3) / 4, 256>>>(AGGh, H, 0, CH);
    cudaEventRecord(evP0, 0);
    cudaStreamWaitEvent(s1, evP0, 0);
    gemm_cp<true, false, false><<<dim3(2, CH / 128), 256, GEMM_SMEM_BYTES, s1>>>(
        H, WT, gc2_bias, out, NI, CH, 256);

    spmm_plain<<<(CH + 3) / 4, 256>>>(AGGh, H, CH, 2 * CH);
    cudaEventRecord(evP1, 0);
    cudaStreamWaitEvent(s1, evP1, 0);
    gemm_cp<true, false, false><<<dim3(2, CH / 128), 256, GEMM_SMEM_BYTES, s1>>>(
        H + (size_t)CH * HID, WT, gc2_bias, out + (size_t)CH * HID, NI + CH, CH, 256);
    cudaEventRecord(evG, s1);

    spmm_plain<<<(N_NODES - 2 * CH + 3) / 4, 256>>>(AGGh, H, 2 * CH, N_NODES);
    gemm_cp<true, false, false><<<dim3(2, (N_NODES - 2 * CH + 127) / 128), 256, GEMM_SMEM_BYTES>>>(
        H + (size_t)(2 * CH) * HID, WT, gc2_bias, out + (size_t)(2 * CH) * HID,
        NI + 2 * CH, N_NODES - 2 * CH, 256);

    cudaStreamWaitEvent(0, evG, 0);
    tail_kernel<<<1, 32>>>(semantic_weight, out, out_size - 5);
}

// round 17
// speedup vs baseline: 1.6975x; 1.0762x over previous
#include <cuda_runtime.h>
#include <cuda_fp16.h>
#include <cstdint>

#define N_NODES 100000
#define N_EDGES 300000
#define HID 256
#define SCAN_B 1024
#define N_BLK ((N_NODES + SCAN_B - 1) / SCAN_B)   // 98

// GEMM pipeline: 4 stages. B stage = 2560 floats (10240B).
// A stage: fp32 = 10240B, fp16 = 128*24*2 = 6144B.
#define BSTAGE_B 10240
#define GEMM_STAGES 4
#define GEMM_SMEM_MAX (4 * 10240 * 2)   // 81920 (fp32-A variant)

// layer-2 chunking (3 chunks)
#define CH 33408   // multiple of 128

// ---------------- scratch ----------------
__device__ __half g_Hh[(size_t)N_NODES * HID];    // fc outputs (fp16)
__device__ __half g_AGGh[(size_t)N_NODES * HID];  // layer-1 output (fp16)
__device__ __half g_H2h[(size_t)N_NODES * HID];   // layer-2 agg (fp16)
__device__ float g_WT[HID * HID];
__device__ float g_W0[HID * 512];
__device__ float g_W1[HID * 256];
__device__ float g_W2[HID * 128];
__device__ float g_norm_out[N_NODES];
__device__ float g_norm_in[N_NODES];
__device__ int g_din[N_NODES];
__device__ int g_dout[N_NODES];
__device__ int g_row_ptr[N_NODES + 1];
__device__ int g_cursor[N_NODES];
__device__ int g_col[N_EDGES];
__device__ int g_blksum[N_BLK];

__device__ __forceinline__ float tf32_rn(float x) {
    uint32_t r;
    asm("cvt.rna.tf32.f32 %0, %1;" : "=r"(r) : "f"(x));
    return __uint_as_float(r);
}
__device__ __forceinline__ void mma_tf32(float* c, const float* a, const float* b) {
    asm volatile(
        "mma.sync.aligned.m16n8k8.row.col.f32.tf32.tf32.f32 "
        "{%0,%1,%2,%3}, {%4,%5,%6,%7}, {%8,%9}, {%0,%1,%2,%3};"
        : "+f"(c[0]), "+f"(c[1]), "+f"(c[2]), "+f"(c[3])
        : "r"(__float_as_uint(a[0])), "r"(__float_as_uint(a[1])),
          "r"(__float_as_uint(a[2])), "r"(__float_as_uint(a[3])),
          "r"(__float_as_uint(b[0])), "r"(__float_as_uint(b[1])));
}
// 8 halves (uint4) -> 8 floats
__device__ __forceinline__ void h8_to_f8(uint4 q, float* f) {
    __half2 h0 = *reinterpret_cast<__half2*>(&q.x);
    __half2 h1 = *reinterpret_cast<__half2*>(&q.y);
    __half2 h2 = *reinterpret_cast<__half2*>(&q.z);
    __half2 h3 = *reinterpret_cast<__half2*>(&q.w);
    float2 a = __half22float2(h0), b = __half22float2(h1);
    float2 c = __half22float2(h2), d = __half22float2(h3);
    f[0] = a.x; f[1] = a.y; f[2] = b.x; f[3] = b.y;
    f[4] = c.x; f[5] = c.y; f[6] = d.x; f[7] = d.y;
}
__device__ __forceinline__ uint4 f8_to_h8(const float* f) {
    __half2 h0 = __floats2half2_rn(f[0], f[1]);
    __half2 h1 = __floats2half2_rn(f[2], f[3]);
    __half2 h2 = __floats2half2_rn(f[4], f[5]);
    __half2 h3 = __floats2half2_rn(f[6], f[7]);
    uint4 q;
    q.x = *reinterpret_cast<uint32_t*>(&h0);
    q.y = *reinterpret_cast<uint32_t*>(&h1);
    q.z = *reinterpret_cast<uint32_t*>(&h2);
    q.w = *reinterpret_cast<uint32_t*>(&h3);
    return q;
}

// ---------------- weight pre-conversion ----------------
__global__ void cvt_weights(const float* __restrict__ W, float* __restrict__ out, int n4) {
    int i = blockIdx.x * blockDim.x + threadIdx.x;
    if (i < n4) {
        float4 v = reinterpret_cast<const float4*>(W)[i];
        v.x = tf32_rn(v.x); v.y = tf32_rn(v.y); v.z = tf32_rn(v.z); v.w = tf32_rn(v.w);
        reinterpret_cast<float4*>(out)[i] = v;
    }
}

// ---------------- CSR build ----------------
__global__ void hist_kernel(const int* __restrict__ src, const int* __restrict__ dst) {
    int e = blockIdx.x * blockDim.x + threadIdx.x;
    if (e < N_EDGES) {
        atomicAdd(&g_dout[src[e]], 1);
        atomicAdd(&g_din[dst[e]], 1);
    }
}
__global__ void scan_a() {
    __shared__ int sh[SCAN_B];
    int t = threadIdx.x, idx = blockIdx.x * SCAN_B + t;
    int v = (idx < N_NODES) ? g_din[idx] : 0;
    sh[t] = v;
    __syncthreads();
#pragma unroll
    for (int off = 1; off < SCAN_B; off <<= 1) {
        int add = (t >= off) ? sh[t - off] : 0;
        __syncthreads();
        sh[t] += add;
        __syncthreads();
    }
    if (idx < N_NODES) g_row_ptr[idx + 1] = sh[t];
    if (t == SCAN_B - 1) g_blksum[blockIdx.x] = sh[t];
}
__global__ void scan_c() {
    __shared__ int red[256];
    const int t = threadIdx.x;
    const int chunk = (blockIdx.x * 256) / SCAN_B;
    int part = 0;
    for (int i = t; i < chunk; i += 256) part += g_blksum[i];
    red[t] = part;
    __syncthreads();
#pragma unroll
    for (int o = 128; o > 0; o >>= 1) {
        if (t < o) red[t] += red[t + o];
        __syncthreads();
    }
    const int base = red[0];
    int idx = blockIdx.x * 256 + t;
    if (idx == 0) g_row_ptr[0] = 0;
    if (idx < N_NODES) {
        int inc = g_row_ptr[idx + 1] + base;
        g_row_ptr[idx + 1] = inc;
        g_cursor[idx] = inc - g_din[idx];
        g_norm_in[idx]  = rsqrtf(fmaxf((float)g_din[idx], 1.f));
        g_norm_out[idx] = rsqrtf(fmaxf((float)g_dout[idx], 1.f));
    }
}
__global__ void scatter_kernel(const int* __restrict__ src, const int* __restrict__ dst) {
    int e = blockIdx.x * blockDim.x + threadIdx.x;
    if (e < N_EDGES) {
        int pos = atomicAdd(&g_cursor[dst[e]], 1);
        g_col[pos] = src[e];
    }
}

// ---------------- CSR SpMM (layer 1): 1 warp/node, uint4 fp16 gathers ----------------
__global__ void __launch_bounds__(256)
spmm_scaled(const __half* __restrict__ X, __half* __restrict__ out,
            const float* __restrict__ bias) {
    int node = blockIdx.x * 8 + (threadIdx.x >> 5);
    if (node >= N_NODES) return;
    int lane = threadIdx.x & 31;
    int beg = g_row_ptr[node], end = g_row_ptr[node + 1];
    float acc[8];
#pragma unroll
    for (int j = 0; j < 8; j++) acc[j] = 0.f;
    for (int base = beg; base < end; base += 4) {
        int last = end - 1;
        int e0 = base;
        int e1 = (base + 1 < end) ? base + 1 : last;
        int e2 = (base + 2 < end) ? base + 2 : last;
        int e3 = (base + 3 < end) ? base + 3 : last;
        float m1 = (base + 1 < end) ? 1.f : 0.f;
        float m2 = (base + 2 < end) ? 1.f : 0.f;
        float m3 = (base + 3 < end) ? 1.f : 0.f;
        int s0 = __ldg(&g_col[e0]), s1 = __ldg(&g_col[e1]);
        int s2 = __ldg(&g_col[e2]), s3 = __ldg(&g_col[e3]);
        float w0 = __ldg(&g_norm_out[s0]);
        float w1 = __ldg(&g_norm_out[s1]) * m1;
        float w2 = __ldg(&g_norm_out[s2]) * m2;
        float w3 = __ldg(&g_norm_out[s3]) * m3;
        uint4 q0 = __ldg(reinterpret_cast<const uint4*>(X + (size_t)s0 * HID) + lane);
        uint4 q1 = __ldg(reinterpret_cast<const uint4*>(X + (size_t)s1 * HID) + lane);
        uint4 q2 = __ldg(reinterpret_cast<const uint4*>(X + (size_t)s2 * HID) + lane);
        uint4 q3 = __ldg(reinterpret_cast<const uint4*>(X + (size_t)s3 * HID) + lane);
        float f0[8], f1[8], f2[8], f3[8];
        h8_to_f8(q0, f0); h8_to_f8(q1, f1); h8_to_f8(q2, f2); h8_to_f8(q3, f3);
#pragma unroll
        for (int j = 0; j < 8; j++)
            acc[j] += f0[j] * w0 + f1[j] * w1 + f2[j] * w2 + f3[j] * w3;
    }
    float ni = g_norm_in[node];
    float no = g_norm_out[node];
    float4 b0 = *reinterpret_cast<const float4*>(bias + lane * 8);
    float4 b1 = *reinterpret_cast<const float4*>(bias + lane * 8 + 4);
    const float* bb = &b0.x;   // b0..b1 contiguous on stack
    float bv[8] = {b0.x, b0.y, b0.z, b0.w, b1.x, b1.y, b1.z, b1.w};
    (void)bb;
#pragma unroll
    for (int j = 0; j < 8; j++)
        acc[j] = fmaxf(acc[j] * ni + bv[j], 0.f) * no;
    reinterpret_cast<uint4*>(out + (size_t)node * HID)[lane] = f8_to_h8(acc);
}

// ---------------- CSR SpMM (layer 2): 1 warp/node, fp16 in/out ----------------
__global__ void __launch_bounds__(256)
spmm_plain(const __half* __restrict__ X, __half* __restrict__ out, int lo, int hi) {
    int node = lo + blockIdx.x * 8 + (threadIdx.x >> 5);
    if (node >= hi) return;
    int lane = threadIdx.x & 31;
    int beg = g_row_ptr[node], end = g_row_ptr[node + 1];
    float acc[8];
#pragma unroll
    for (int j = 0; j < 8; j++) acc[j] = 0.f;
    for (int base = beg; base < end; base += 4) {
        int last = end - 1;
        int e0 = base;
        int e1 = (base + 1 < end) ? base + 1 : last;
        int e2 = (base + 2 < end) ? base + 2 : last;
        int e3 = (base + 3 < end) ? base + 3 : last;
        float m1 = (base + 1 < end) ? 1.f : 0.f;
        float m2 = (base + 2 < end) ? 1.f : 0.f;
        float m3 = (base + 3 < end) ? 1.f : 0.f;
        int s0 = __ldg(&g_col[e0]), s1 = __ldg(&g_col[e1]);
        int s2 = __ldg(&g_col[e2]), s3 = __ldg(&g_col[e3]);
        uint4 q0 = __ldg(reinterpret_cast<const uint4*>(X + (size_t)s0 * HID) + lane);
        uint4 q1 = __ldg(reinterpret_cast<const uint4*>(X + (size_t)s1 * HID) + lane);
        uint4 q2 = __ldg(reinterpret_cast<const uint4*>(X + (size_t)s2 * HID) + lane);
        uint4 q3 = __ldg(reinterpret_cast<const uint4*>(X + (size_t)s3 * HID) + lane);
        float f0[8], f1[8], f2[8], f3[8];
        h8_to_f8(q0, f0); h8_to_f8(q1, f1); h8_to_f8(q2, f2); h8_to_f8(q3, f3);
#pragma unroll
        for (int j = 0; j < 8; j++)
            acc[j] += f0[j] + f1[j] * m1 + f2[j] * m2 + f3[j] * m3;
    }
    reinterpret_cast<uint4*>(out + (size_t)node * HID)[lane] = f8_to_h8(acc);
}

// ---------------- tensor-core GEMM: cp.async 4-stage pipeline ----------------
// AH: A is fp16 (converted post-LDS; exact in tf32). Otherwise fp32, rounded iff CVTA.
// HOUT: fp16 output.
template<bool RELU, bool CVTA, bool AH, bool HOUT>
__global__ void __launch_bounds__(256, 2)
gemm_cp(const void* __restrict__ Av, const float* __restrict__ B,
        const float* __restrict__ bias, float* __restrict__ C,
        const float* __restrict__ rscale, int M, int K) {
    extern __shared__ float sm[];
    char* smc = reinterpret_cast<char*>(sm);
    const uint32_t smem_base = (uint32_t)__cvta_generic_to_shared(sm);

    constexpr int ASTAGE_B = AH ? 6144 : 10240;   // fp16: 128*24*2
    constexpr int BOFF = GEMM_STAGES * ASTAGE_B;

    const int tid = threadIdx.x;
    const int lane = tid & 31;
    const int wid = tid >> 5;
    const int wm = (wid & 1) * 64;
    const int wn = (wid >> 1) * 32;
    const int gid = lane >> 2;
    const int tig = lane & 3;
    const int bm = blockIdx.y * 128;
    const int bn = blockIdx.x * 128;

    // B copy coords (2 slots of float4)
    const int r0 = tid >> 2, r1 = (tid + 256) >> 2;
    const int c40 = (tid & 3) * 4;
    const float* b_src0 = B + (size_t)(bn + r0) * K + c40;
    const float* b_src1 = B + (size_t)(bn + r1) * K + c40;
    const uint32_t b_off0 = (uint32_t)((r0 * 20 + c40) * 4);
    const uint32_t b_off1 = (uint32_t)((r1 * 20 + c40) * 4);

    // A copy coords
    const float* a_srcf0 = nullptr; const float* a_srcf1 = nullptr;
    const __half* a_srch = nullptr;
    int aszf0 = 0, aszf1 = 0, aszh = 0;
    uint32_t a_offf0 = 0, a_offf1 = 0, a_offh = 0;
    if (AH) {
        const __half* Ah = (const __half*)Av;
        int rA = tid >> 1, cA = (tid & 1) * 8;      // 256 threads x 16B = full tile
        int ga = bm + rA;
        a_srch = Ah + (size_t)(ga < M ? ga : (M - 1)) * K + cA;
        aszh = (ga < M) ? 16 : 0;
        a_offh = (uint32_t)((rA * 24 + cA) * 2);
    } else {
        const float* Af = (const float*)Av;
        int ga0 = bm + r0, ga1 = bm + r1;
        a_srcf0 = Af + (size_t)(ga0 < M ? ga0 : (M - 1)) * K + c40;
        a_srcf1 = Af + (size_t)(ga1 < M ? ga1 : (M - 1)) * K + c40;
        aszf0 = (ga0 < M) ? 16 : 0;
        aszf1 = (ga1 < M) ? 16 : 0;
        a_offf0 = (uint32_t)((r0 * 20 + c40) * 4);
        a_offf1 = (uint32_t)((r1 * 20 + c40) * 4);
    }

    auto issue_stage = [&](int st, int k0) {
        uint32_t abase = smem_base + (uint32_t)(st * ASTAGE_B);
        uint32_t bbase = smem_base + (uint32_t)(BOFF + st * BSTAGE_B);
        if (AH) {
            asm volatile("cp.async.cg.shared.global [%0], [%1], 16, %2;"
                         :: "r"(abase + a_offh), "l"(a_srch + k0), "r"(aszh));
        } else {
            asm volatile("cp.async.cg.shared.global [%0], [%1], 16, %2;"
                         :: "r"(abase + a_offf0), "l"(a_srcf0 + k0), "r"(aszf0));
            asm volatile("cp.async.cg.shared.global [%0], [%1], 16, %2;"
                         :: "r"(abase + a_offf1), "l"(a_srcf1 + k0), "r"(aszf1));
        }
        asm volatile("cp.async.cg.shared.global [%0], [%1], 16;"
                     :: "r"(bbase + b_off0), "l"(b_src0 + k0));
        asm volatile("cp.async.cg.shared.global [%0], [%1], 16;"
                     :: "r"(bbase + b_off1), "l"(b_src1 + k0));
        asm volatile("cp.async.commit_group;");
    };

    float acc[4][4][4];
#pragma unroll
    for (int i = 0; i < 4; i++)
#pragma unroll
        for (int j = 0; j < 4; j++)
#pragma unroll
            for (int v = 0; v < 4; v++) acc[i][j][v] = 0.f;

    const int nIt = K >> 4;

    issue_stage(0, 0);
    issue_stage(1, 16);
    issue_stage(2, 32);
    asm volatile("cp.async.wait_group 2;");
    __syncthreads();

    for (int it = 0; it < nIt; it++) {
        const int s = it % GEMM_STAGES;
        const float* Bs = reinterpret_cast<const float*>(smc + BOFF + s * BSTAGE_B);

#pragma unroll
        for (int kk = 0; kk < 2; kk++) {
            const int kb = kk * 8;
            float a[4][4], b[4][2];
            if (AH) {
                const __half* AsH = reinterpret_cast<const __half*>(smc + s * ASTAGE_B);
#pragma unroll
                for (int i = 0; i < 4; i++) {
                    const __half* p = AsH + (wm + i * 16 + gid) * 24 + kb + tig;
                    a[i][0] = __half2float(p[0]);
                    a[i][1] = __half2float(p[8 * 24]);
                    a[i][2] = __half2float(p[4]);
                    a[i][3] = __half2float(p[8 * 24 + 4]);
                }
            } else {
                const float* AsF = reinterpret_cast<const float*>(smc + s * ASTAGE_B);
#pragma unroll
                for (int i = 0; i < 4; i++) {
                    const float* p = &AsF[(wm + i * 16 + gid) * 20 + kb + tig];
                    a[i][0] = p[0];
                    a[i][1] = p[8 * 20];
                    a[i][2] = p[4];
                    a[i][3] = p[8 * 20 + 4];
                    if (CVTA) {
                        a[i][0] = tf32_rn(a[i][0]); a[i][1] = tf32_rn(a[i][1]);
                        a[i][2] = tf32_rn(a[i][2]); a[i][3] = tf32_rn(a[i][3]);
                    }
                }
            }
#pragma unroll
            for (int j = 0; j < 4; j++) {
                const float* p = &Bs[(wn + j * 8 + gid) * 20 + kb + tig];
                b[j][0] = p[0];
                b[j][1] = p[4];
            }
#pragma unroll
            for (int i = 0; i < 4; i++)
#pragma unroll
                for (int j = 0; j < 4; j++)
                    mma_tf32(acc[i][j], a[i], b[j]);
        }

        const int nx = it + 3;
        if (nx < nIt) issue_stage(nx % GEMM_STAGES, nx * 16);
        else asm volatile("cp.async.commit_group;");
        asm volatile("cp.async.wait_group 2;");
        __syncthreads();
    }

#pragma unroll
    for (int j = 0; j < 4; j++) {
        const int col = bn + wn + j * 8 + tig * 2;
        const float bx = bias[col], by = bias[col + 1];
#pragma unroll
        for (int i = 0; i < 4; i++) {
            const int ra = bm + wm + i * 16 + gid;
            const int rb = ra + 8;
            if (ra < M) {
                float s = rscale ? rscale[ra] : 1.f;
                float2 v;
                v.x = acc[i][j][0] * s + bx;
                v.y = acc[i][j][1] * s + by;
                if (RELU) { v.x = fmaxf(v.x, 0.f); v.y = fmaxf(v.y, 0.f); }
                if (HOUT) {
                    __half2 h = __floats2half2_rn(v.x, v.y);
                    *reinterpret_cast<__half2*>(reinterpret_cast<__half*>(C) + (size_t)ra * HID + col) = h;
                } else {
                    *reinterpret_cast<float2*>(C + (size_t)ra * HID + col) = v;
                }
            }
            if (rb < M) {
                float s = rscale ? rscale[rb] : 1.f;
                float2 v;
                v.x = acc[i][j][2] * s + bx;
                v.y = acc[i][j][3] * s + by;
                if (RELU) { v.x = fmaxf(v.x, 0.f); v.y = fmaxf(v.y, 0.f); }
                if (HOUT) {
                    __half2 h = __floats2half2_rn(v.x, v.y);
                    *reinterpret_cast<__half2*>(reinterpret_cast<__half*>(C) + (size_t)rb * HID + col) = h;
                } else {
                    *reinterpret_cast<float2*>(C + (size_t)rb * HID + col) = v;
                }
            }
        }
    }
}

// ---------------- transpose gc2_weight [K,N] -> g_WT [N,K], tf32-rounded ----------------
__global__ void transpose_kernel(const float* __restrict__ W) {
    __shared__ float t[32][33];
    int bx = blockIdx.x * 32, by = blockIdx.y * 32;
    t[threadIdx.y][threadIdx.x] = W[(size_t)(by + threadIdx.y) * HID + bx + threadIdx.x];
    __syncthreads();
    g_WT[(size_t)(bx + threadIdx.y) * HID + by + threadIdx.x] = tf32_rn(t[threadIdx.x][threadIdx.y]);
}

__global__ void tail_kernel(const float* __restrict__ sw, float* __restrict__ out, int off) {
    if (threadIdx.x < 5) out[off + threadIdx.x] = sw[threadIdx.x];
}

// ---------------- launch ----------------
extern "C" void kernel_launch(void* const* d_in, const int* in_sizes, int n_in,
                              void* d_out, int out_size) {
    const float* feat0 = (const float*)d_in[0];
    const float* feat1 = (const float*)d_in[1];
    const float* feat2 = (const float*)d_in[2];
    const float* fc_w0 = (const float*)d_in[3];
    const float* fc_b0 = (const float*)d_in[4];
    const float* fc_w1 = (const float*)d_in[5];
    const float* fc_b1 = (const float*)d_in[6];
    const float* fc_w2 = (const float*)d_in[7];
    const float* fc_b2 = (const float*)d_in[8];
    const float* gc1_bias = (const float*)d_in[9];
    const float* gc2_weight = (const float*)d_in[10];
    const float* gc2_bias = (const float*)d_in[11];
    const float* semantic_weight = (const float*)d_in[12];
    const int* src = (const int*)d_in[13];   // JAX x64-disabled -> int32
    const int* dst = (const int*)d_in[14];
    float* out = (float*)d_out;

    float *WT = nullptr, *NI = nullptr;
    float *W0 = nullptr, *W1 = nullptr, *W2 = nullptr;
    __half *Hh = nullptr, *AGGh = nullptr, *H2h = nullptr;
    void *DIN = nullptr, *DOUT = nullptr;
    cudaGetSymbolAddress((void**)&Hh, g_Hh);
    cudaGetSymbolAddress((void**)&AGGh, g_AGGh);
    cudaGetSymbolAddress((void**)&H2h, g_H2h);
    cudaGetSymbolAddress((void**)&WT, g_WT);
    cudaGetSymbolAddress((void**)&NI, g_norm_in);
    cudaGetSymbolAddress((void**)&W0, g_W0);
    cudaGetSymbolAddress((void**)&W1, g_W1);
    cudaGetSymbolAddress((void**)&W2, g_W2);
    cudaGetSymbolAddress(&DIN, g_din);
    cudaGetSymbolAddress(&DOUT, g_dout);

    static cudaStream_t sPrep = nullptr, s1 = nullptr, s2 = nullptr;
    static cudaEvent_t evFork = nullptr, evJoin = nullptr, ev1 = nullptr, ev2 = nullptr;
    static cudaEvent_t evP0 = nullptr, evP1 = nullptr, evG = nullptr;
    if (sPrep == nullptr) {
        cudaStreamCreateWithFlags(&sPrep, cudaStreamNonBlocking);
        cudaStreamCreateWithFlags(&s1, cudaStreamNonBlocking);
        cudaStreamCreateWithFlags(&s2, cudaStreamNonBlocking);
        cudaEventCreateWithFlags(&evFork, cudaEventDisableTiming);
        cudaEventCreateWithFlags(&evJoin, cudaEventDisableTiming);
        cudaEventCreateWithFlags(&ev1, cudaEventDisableTiming);
        cudaEventCreateWithFlags(&ev2, cudaEventDisableTiming);
        cudaEventCreateWithFlags(&evP0, cudaEventDisableTiming);
        cudaEventCreateWithFlags(&evP1, cudaEventDisableTiming);
        cudaEventCreateWithFlags(&evG, cudaEventDisableTiming);
        cudaFuncSetAttribute(gemm_cp<false, true, false, true>, cudaFuncAttributeMaxDynamicSharedMemorySize, GEMM_SMEM_MAX);
        cudaFuncSetAttribute(gemm_cp<true, false, true, false>, cudaFuncAttributeMaxDynamicSharedMemorySize, GEMM_SMEM_MAX);
    }

    cudaEventRecord(evFork, 0);
    cudaStreamWaitEvent(sPrep, evFork, 0);
    cudaStreamWaitEvent(s1, evFork, 0);
    cudaStreamWaitEvent(s2, evFork, 0);

    // ---- s1: fc1 branch (fp16 output) ----
    cvt_weights<<<(HID * 256 / 4 + 255) / 256, 256, 0, s1>>>(fc_w1, W1, HID * 256 / 4);
    gemm_cp<false, true, false, true><<<dim3(2, (30000 + 127) / 128), 256, GEMM_SMEM_MAX, s1>>>(
        feat1, W1, fc_b1, (float*)(Hh + (size_t)40000 * HID), nullptr, 30000, 256);
    cudaEventRecord(ev1, s1);

    // ---- s2: fc2 branch ----
    cvt_weights<<<(HID * 128 / 4 + 255) / 256, 256, 0, s2>>>(fc_w2, W2, HID * 128 / 4);
    gemm_cp<false, true, false, true><<<dim3(2, (30000 + 127) / 128), 256, GEMM_SMEM_MAX, s2>>>(
        feat2, W2, fc_b2, (float*)(Hh + (size_t)70000 * HID), nullptr, 30000, 128);
    cudaEventRecord(ev2, s2);

    // ---- main: fc0 branch ----
    cvt_weights<<<(HID * 512 / 4 + 255) / 256, 256>>>(fc_w0, W0, HID * 512 / 4);
    gemm_cp<false, true, false, true><<<dim3(2, (40000 + 127) / 128), 256, GEMM_SMEM_MAX>>>(
        feat0, W0, fc_b0, (float*)Hh, nullptr, 40000, 512);

    // ---- prep stream: CSR build + norms + weight transpose ----
    cudaMemsetAsync(DIN, 0, N_NODES * sizeof(int), sPrep);
    cudaMemsetAsync(DOUT, 0, N_NODES * sizeof(int), sPrep);
    hist_kernel<<<(N_EDGES + 255) / 256, 256, 0, sPrep>>>(src, dst);
    scan_a<<<N_BLK, SCAN_B, 0, sPrep>>>();
    scan_c<<<(N_NODES + 255) / 256, 256, 0, sPrep>>>();
    scatter_kernel<<<(N_EDGES + 255) / 256, 256, 0, sPrep>>>(src, dst);
    transpose_kernel<<<dim3(8, 8), dim3(32, 32), 0, sPrep>>>(gc2_weight);
    cudaEventRecord(evJoin, sPrep);

    // ---- join all branches on main ----
    cudaStreamWaitEvent(0, ev1, 0);
    cudaStreamWaitEvent(0, ev2, 0);
    cudaStreamWaitEvent(0, evJoin, 0);

    // layer 1 SpMM (full, fp16 in/out, warp per node)
    spmm_scaled<<<(N_NODES + 7) / 8, 256>>>(Hh, AGGh, gc1_bias);

    // layer 2: 3-chunk pipelined SpMM (main, fp16 out) -> GEMM (s1, fp16 A)
    spmm_plain<<<(CH + 7) / 8, 256>>>(AGGh, H2h, 0, CH);
    cudaEventRecord(evP0, 0);
    cudaStreamWaitEvent(s1, evP0, 0);
    gemm_cp<true, false, true, false><<<dim3(2, CH / 128), 256, GEMM_SMEM_MAX, s1>>>(
        H2h, WT, gc2_bias, out, NI, CH, 256);

    spmm_plain<<<(CH + 7) / 8, 256>>>(AGGh, H2h, CH, 2 * CH);
    cudaEventRecord(evP1, 0);
    cudaStreamWaitEvent(s1, evP1, 0);
    gemm_cp<true, false, true, false><<<dim3(2, CH / 128), 256, GEMM_SMEM_MAX, s1>>>(
        H2h + (size_t)CH * HID, WT, gc2_bias, out + (size_t)CH * HID, NI + CH, CH, 256);
    cudaEventRecord(evG, s1);

    spmm_plain<<<(N_NODES - 2 * CH + 7) / 8, 256>>>(AGGh, H2h, 2 * CH, N_NODES);
    gemm_cp<true, false, true, false><<<dim3(2, (N_NODES - 2 * CH + 127) / 128), 256, GEMM_SMEM_MAX>>>(
        H2h + (size_t)(2 * CH) * HID, WT, gc2_bias, out + (size_t)(2 * CH) * HID,
        NI + 2 * CH, N_NODES - 2 * CH, 256);

    cudaStreamWaitEvent(0, evG, 0);
    tail_kernel<<<1, 32>>>(semantic_weight, out, out_size - 5);
}